// round 15
// baseline (speedup 1.0000x reference)
#include <cuda_runtime.h>
#include <cuda_bf16.h>
#include <math.h>
#include <stdint.h>

#define B_ 32
#define S_ 1024
#define D_ 768
#define L_ 12
#define MTOT (B_*S_)
#define NAUG 1536                    // [M(768) | Wv(768)]
#define VOFF 768
#define LB ((long)D_*NAUG)           // per-layer Baug stride

// ===================== scratch (__device__ globals; no allocs) =====================
__device__ __align__(16) __nv_bfloat16 g_hh  [(size_t)MTOT*D_];
__device__ __align__(16) __nv_bfloat16 g_hl  [(size_t)MTOT*D_];
__device__ __align__(16) __nv_bfloat16 g_GVh [(size_t)MTOT*NAUG];   // [G | V]
__device__ __align__(16) __nv_bfloat16 g_GVl [(size_t)MTOT*NAUG];
__device__ __align__(16) float         g_P   [(size_t)B_*S_*S_];
__device__ __align__(16) __nv_bfloat16 g_Ph  [(size_t)B_*S_*S_];
__device__ __align__(16) __nv_bfloat16 g_Pl  [(size_t)B_*S_*S_];
__device__ __align__(16) __nv_bfloat16 g_Baugh[(size_t)L_*D_*NAUG];
__device__ __align__(16) __nv_bfloat16 g_Baugl[(size_t)L_*D_*NAUG];
__device__ __align__(16) __nv_bfloat16 g_Wqsh[(size_t)L_*D_*D_];    // Wq split (straight)
__device__ __align__(16) __nv_bfloat16 g_Wqsl[(size_t)L_*D_*D_];
__device__ __align__(16) __nv_bfloat16 g_Wksh[(size_t)L_*D_*D_];    // Wk*lk split
__device__ __align__(16) __nv_bfloat16 g_Wksl[(size_t)L_*D_*D_];
__device__ float g_biasVG[(size_t)L_*NAUG];
__device__ float g_cscVG [(size_t)L_*NAUG];
__device__ float g_w1[(size_t)L_*D_];    // alpha * Wq (lk .* bk)
__device__ float g_w2[(size_t)L_*D_];    // alpha * Wk (lk .* bq)
__device__ float g_U[MTOT];
__device__ float g_W[MTOT];
__device__ float g_c[L_];

// ===================== PTX helpers (generic sm_80+ features only) =====================
__device__ __forceinline__ uint32_t smem_u32(const void* p) {
    uint32_t a;
    asm("{ .reg .u64 t; cvta.to.shared.u64 t, %1; cvt.u32.u64 %0, t; }" : "=r"(a) : "l"(p));
    return a;
}
__device__ __forceinline__ void cpa16(uint32_t s, const void* g) {
    asm volatile("cp.async.cg.shared.global [%0], [%1], 16;" :: "r"(s), "l"(g));
}
#define CP_COMMIT() asm volatile("cp.async.commit_group;" ::: "memory")
#define CP_WAIT1()  asm volatile("cp.async.wait_group 1;" ::: "memory")

__device__ __forceinline__ void ldm_x4(uint32_t& r0, uint32_t& r1, uint32_t& r2, uint32_t& r3,
                                       uint32_t a) {
    asm volatile("ldmatrix.sync.aligned.m8n8.x4.shared.b16 {%0,%1,%2,%3}, [%4];"
                 : "=r"(r0), "=r"(r1), "=r"(r2), "=r"(r3) : "r"(a));
}
__device__ __forceinline__ void ldm_x4t(uint32_t& r0, uint32_t& r1, uint32_t& r2, uint32_t& r3,
                                        uint32_t a) {
    asm volatile("ldmatrix.sync.aligned.m8n8.x4.trans.shared.b16 {%0,%1,%2,%3}, [%4];"
                 : "=r"(r0), "=r"(r1), "=r"(r2), "=r"(r3) : "r"(a));
}
__device__ __forceinline__ void mma_bf16(float* c, const uint32_t* a, const uint32_t* b) {
    asm volatile("mma.sync.aligned.m16n8k16.row.col.f32.bf16.bf16.f32 "
                 "{%0,%1,%2,%3}, {%4,%5,%6,%7}, {%8,%9}, {%0,%1,%2,%3};"
                 : "+f"(c[0]), "+f"(c[1]), "+f"(c[2]), "+f"(c[3])
                 : "r"(a[0]), "r"(a[1]), "r"(a[2]), "r"(a[3]), "r"(b[0]), "r"(b[1]));
}

// ===================== GEMM ==============
// BTRANS=0: Bt [N,K] row-major (NT).   BTRANS=1: B [K,N] row-major (NN, trans-ldmatrix).
// A: [M,K] row-major split (Ah,Al).  bf16x3: acc += AhBh + AhBl + AlBh (fp32 accum).
// OUT=0: fp32 C.  OUT=1: bf16 hi/lo split (Ch, Cl).
#define BM 128
#define BN 128
#define BKE 32
#define ROWB 80
#define TILEB (128 * ROWB)            // 10240 B
#define BT_ROWB 272                   // 256B + 16B pad; 17 units mod 8 = 1
#define BT_TILE (32 * BT_ROWB)        // 8704 B

template<int OUT, int BTRANS>
__global__ __launch_bounds__(256, 2)
void gemm_mma(const __nv_bfloat16* __restrict__ Ah, const __nv_bfloat16* __restrict__ Al,
              const __nv_bfloat16* __restrict__ Bh, const __nv_bfloat16* __restrict__ Bl,
              float* __restrict__ Cf,
              __nv_bfloat16* __restrict__ Ch, __nv_bfloat16* __restrict__ Cl,
              const float* __restrict__ bias, const float* __restrict__ csc,
              float alpha, int K, int lda, int ldb, int ldc,
              long sA, long sB, long sC)
{
    constexpr int BTILEB = BTRANS ? BT_TILE : TILEB;
    constexpr int STAGEB = 2 * TILEB + 2 * BTILEB;

    extern __shared__ char smem[];
    const uint32_t sbase = smem_u32(smem);
    const int tid = threadIdx.x;
    const int lane = tid & 31, wid = tid >> 5;
    const int wm = wid & 3, wn = wid >> 2;
    const int z = blockIdx.z;
    Ah += z * sA;  Al += z * sA;
    Bh += z * sB;  Bl += z * sB;

    const long tileM = blockIdx.y * (long)BM;
    const long tileN = blockIdx.x * (long)BN;

    const __nv_bfloat16* gAh = Ah + tileM * lda;
    const __nv_bfloat16* gAl = Al + tileM * lda;
    const __nv_bfloat16* gBh = BTRANS ? Bh : (Bh + tileN * ldb);
    const __nv_bfloat16* gBl = BTRANS ? Bl : (Bl + tileN * ldb);

    const int r0q = tid >> 2, c0q = tid & 3;

    auto load_stage = [&](int stage, int k0) {
        const uint32_t sb = sbase + stage * STAGEB;
        #pragma unroll
        for (int it = 0; it < 2; it++) {
            const int r = r0q + it * 64;
            const long go = (long)r * lda + k0 + c0q * 8;
            const uint32_t so = r * ROWB + c0q * 16;
            cpa16(sb + 0 * TILEB + so, gAh + go);
            cpa16(sb + 1 * TILEB + so, gAl + go);
        }
        if (BTRANS) {
            #pragma unroll
            for (int it = 0; it < 2; it++) {
                const int idx = tid + it * 256;
                const int r = idx >> 4, c = idx & 15;
                const long go = (long)(k0 + r) * ldb + tileN + c * 8;
                const uint32_t so = r * BT_ROWB + c * 16;
                cpa16(sb + 2 * TILEB + so, gBh + go);
                cpa16(sb + 2 * TILEB + BTILEB + so, gBl + go);
            }
        } else {
            #pragma unroll
            for (int it = 0; it < 2; it++) {
                const int r = r0q + it * 64;
                const long gb = (long)r * ldb + k0 + c0q * 8;
                const uint32_t so = r * ROWB + c0q * 16;
                cpa16(sb + 2 * TILEB + so, gBh + gb);
                cpa16(sb + 2 * TILEB + BTILEB + so, gBl + gb);
            }
        }
        CP_COMMIT();
    };

    float acc[2][8][4];
    #pragma unroll
    for (int i = 0; i < 2; i++)
        #pragma unroll
        for (int j = 0; j < 8; j++)
            #pragma unroll
            for (int q = 0; q < 4; q++) acc[i][j][q] = 0.f;

    const int nk = K / BKE;
    load_stage(0, 0);
    load_stage(1, BKE);

    const int a_row  = wm * 32 + (lane & 15);
    const int b_row  = wn * 64 + (lane & 7) + ((lane >> 3) & 1) * 8;
    const int colb   = (lane >> 4) * 16;
    const int bt_k   = ((lane >> 4) & 1) * 8 + (lane & 7);
    const int bt_n   = wn * 64 + ((lane >> 3) & 1) * 8;

    for (int i = 0; i < nk; i++) {
        CP_WAIT1();
        __syncthreads();
        const uint32_t sb = sbase + (i & 1) * STAGEB;

        #pragma unroll
        for (int ks = 0; ks < 2; ks++) {
            uint32_t ah[2][4], al[2][4], bh[8][2], bl[8][2];
            #pragma unroll
            for (int ma = 0; ma < 2; ma++) {
                const uint32_t ad = sb + (a_row + ma * 16) * ROWB + ks * 32 + colb;
                ldm_x4(ah[ma][0], ah[ma][1], ah[ma][2], ah[ma][3], ad);
                ldm_x4(al[ma][0], al[ma][1], al[ma][2], al[ma][3], ad + TILEB);
            }
            #pragma unroll
            for (int nb = 0; nb < 4; nb++) {
                uint32_t t0, t1, t2, t3;
                if (BTRANS) {
                    const uint32_t bd = sb + 2 * TILEB
                                      + (ks * 16 + bt_k) * BT_ROWB
                                      + (bt_n + nb * 16) * 2;
                    ldm_x4t(t0, t1, t2, t3, bd);
                    bh[2*nb][0] = t0; bh[2*nb][1] = t2; bh[2*nb+1][0] = t1; bh[2*nb+1][1] = t3;
                    ldm_x4t(t0, t1, t2, t3, bd + BTILEB);
                    bl[2*nb][0] = t0; bl[2*nb][1] = t2; bl[2*nb+1][0] = t1; bl[2*nb+1][1] = t3;
                } else {
                    const uint32_t bd = sb + 2 * TILEB + (b_row + nb * 16) * ROWB + ks * 32 + colb;
                    ldm_x4(t0, t1, t2, t3, bd);
                    bh[2*nb][0] = t0; bh[2*nb][1] = t2; bh[2*nb+1][0] = t1; bh[2*nb+1][1] = t3;
                    ldm_x4(t0, t1, t2, t3, bd + BTILEB);
                    bl[2*nb][0] = t0; bl[2*nb][1] = t2; bl[2*nb+1][0] = t1; bl[2*nb+1][1] = t3;
                }
            }
            #pragma unroll
            for (int ma = 0; ma < 2; ma++)
                #pragma unroll
                for (int na = 0; na < 8; na++) mma_bf16(acc[ma][na], ah[ma], bh[na]);
            #pragma unroll
            for (int ma = 0; ma < 2; ma++)
                #pragma unroll
                for (int na = 0; na < 8; na++) mma_bf16(acc[ma][na], ah[ma], bl[na]);
            #pragma unroll
            for (int ma = 0; ma < 2; ma++)
                #pragma unroll
                for (int na = 0; na < 8; na++) mma_bf16(acc[ma][na], al[ma], bh[na]);
        }

        __syncthreads();
        if (i + 2 < nk) load_stage(i & 1, (i + 2) * BKE);
        else CP_COMMIT();
    }

    // ===================== epilogue =====================
    const int gq = lane >> 2, rq = lane & 3;
    #pragma unroll
    for (int ma = 0; ma < 2; ma++) {
        #pragma unroll
        for (int half = 0; half < 2; half++) {
            const long row = tileM + wm * 32 + ma * 16 + gq + half * 8;
            #pragma unroll
            for (int na = 0; na < 8; na++) {
                const long col = tileN + wn * 64 + na * 8 + rq * 2;
                float v0 = acc[ma][na][half * 2 + 0] * alpha;
                float v1 = acc[ma][na][half * 2 + 1] * alpha;
                if (bias) { v0 += bias[col]; v1 += bias[col + 1]; }
                if (csc)  { v0 *= csc[col];  v1 *= csc[col + 1]; }
                if (OUT == 0) {
                    float2 f2; f2.x = v0; f2.y = v1;
                    *(float2*)(Cf + z * sC + row * ldc + col) = f2;
                } else {
                    const __nv_bfloat16 h0 = __float2bfloat16(v0);
                    const __nv_bfloat16 h1 = __float2bfloat16(v1);
                    const __nv_bfloat16 l0 = __float2bfloat16(v0 - __bfloat162float(h0));
                    const __nv_bfloat16 l1 = __float2bfloat16(v1 - __bfloat162float(h1));
                    __nv_bfloat162 hp; hp.x = h0; hp.y = h1;
                    __nv_bfloat162 lp; lp.x = l0; lp.y = l1;
                    *(__nv_bfloat162*)(Ch + z * sC + row * ldc + col) = hp;
                    *(__nv_bfloat162*)(Cl + z * sC + row * ldc + col) = lp;
                }
            }
        }
    }
}

#define GEMM_SMEM_NT (2 * (2 * TILEB + 2 * TILEB))     // 81920
#define GEMM_SMEM_NN (2 * (2 * TILEB + 2 * BT_TILE))   // 75776

// ===================== elementwise fp32 -> bf16 hi/lo split (contiguous) ============
__global__ __launch_bounds__(256)
void split_kernel(const float* __restrict__ X, __nv_bfloat16* __restrict__ Xh,
                  __nv_bfloat16* __restrict__ Xl)
{
    const long i = ((long)blockIdx.x * 256 + threadIdx.x) * 4;
    const float4 f = *(const float4*)(X + i);
    float v[4] = {f.x, f.y, f.z, f.w};
    __nv_bfloat16 h[4], l[4];
    #pragma unroll
    for (int k = 0; k < 4; k++) {
        h[k] = __float2bfloat16(v[k]);
        l[k] = __float2bfloat16(v[k] - __bfloat162float(h[k]));
    }
    *(uint2*)(Xh + i) = *(const uint2*)h;
    *(uint2*)(Xl + i) = *(const uint2*)l;
}

// ===================== split with optional column scale, strided dst =================
__global__ __launch_bounds__(256)
void split_cs(const float* __restrict__ X, const float* __restrict__ sc,
              __nv_bfloat16* __restrict__ Dh, __nv_bfloat16* __restrict__ Dl,
              int C, int ldD, int off, long sX, long sSc, long sD)
{
    const int z = blockIdx.z;
    X += z * sX;
    if (sc) sc += z * sSc;
    Dh += z * sD;
    Dl += z * sD;
    const long idx = ((long)blockIdx.x * 256 + threadIdx.x) * 4;
    const int r = (int)(idx / C), c = (int)(idx % C);
    const float4 f = *(const float4*)(X + idx);
    float v[4] = {f.x, f.y, f.z, f.w};
    __nv_bfloat16 h[4], l[4];
    #pragma unroll
    for (int k = 0; k < 4; k++) {
        const float s = sc ? sc[c + k] : 1.0f;
        const float x = v[k] * s;
        h[k] = __float2bfloat16(x);
        l[k] = __float2bfloat16(x - __bfloat162float(h[k]));
    }
    const long o = (long)r * ldD + off + c;
    *(uint2*)(Dh + o) = *(const uint2*)h;
    *(uint2*)(Dl + o) = *(const uint2*)l;
}

// ===================== pack VG bias / csc =====================
__global__ __launch_bounds__(256)
void pack_vg(const float* __restrict__ bv, const float* __restrict__ lv,
             float* __restrict__ biasVG, float* __restrict__ cscVG)
{
    const int idx = blockIdx.x * 256 + threadIdx.x;    // over L_*NAUG = 18432 (exact)
    const int l = idx / NAUG, c = idx % NAUG;
    biasVG[idx] = (c >= VOFF) ? bv[l * D_ + (c - VOFF)] : 0.0f;
    cscVG[idx]  = (c >= VOFF) ? lv[l * D_ + (c - VOFF)] : 1.0f;
}

// ===================== bias-correction vectors (fp32) =====================
__global__ __launch_bounds__(256)
void wvec(const float* __restrict__ Wq, const float* __restrict__ Wk,
          const float* __restrict__ bq, const float* __restrict__ bk,
          const float* __restrict__ lk,
          float* __restrict__ w1, float* __restrict__ w2, float alpha)
{
    const int l = blockIdx.z;
    const int d = blockIdx.x * 256 + threadIdx.x;      // grid.x = 3
    const float* wq = Wq + (long)l * D_ * D_ + (long)d * D_;
    const float* wk = Wk + (long)l * D_ * D_ + (long)d * D_;
    const float* bqz = bq + (long)l * D_;
    const float* bkz = bk + (long)l * D_;
    const float* lkz = lk + (long)l * D_;
    float a1 = 0.f, a2 = 0.f;
    for (int e = 0; e < D_; e++) {
        const float le = lkz[e];
        a1 += wq[e] * le * bkz[e];
        a2 += wk[e] * le * bqz[e];
    }
    w1[(long)l * D_ + d] = alpha * a1;
    w2[(long)l * D_ + d] = alpha * a2;
}

// ===================== c constant per layer =====================
__global__ __launch_bounds__(256)
void c_kernel(const float* __restrict__ bq, const float* __restrict__ bk,
              const float* __restrict__ lk, float* __restrict__ cOut, float alpha)
{
    const int l = blockIdx.x;
    const int tid = threadIdx.x;
    __shared__ float red[8];
    float s = 0.f;
    for (int e = tid; e < D_; e += 256)
        s += bq[l * D_ + e] * lk[l * D_ + e] * bk[l * D_ + e];
    #pragma unroll
    for (int o = 16; o; o >>= 1) s += __shfl_xor_sync(0xFFFFFFFFu, s, o);
    if ((tid & 31) == 0) red[tid >> 5] = s;
    __syncthreads();
    if (tid == 0) {
        float t = 0.f;
        #pragma unroll
        for (int w = 0; w < 8; w++) t += red[w];
        cOut[l] = alpha * t;
    }
}

// ===================== u,w per row: dot(h, w1)+c, dot(h, w2) =====================
__global__ __launch_bounds__(256)
void uw_kernel(const __nv_bfloat16* __restrict__ hh, const __nv_bfloat16* __restrict__ hl,
               const float* __restrict__ w1, const float* __restrict__ w2,
               const float* __restrict__ cAll, int l,
               float* __restrict__ U, float* __restrict__ W)
{
    const long row = blockIdx.x;
    const long base = row * D_;
    const int tid = threadIdx.x;
    __shared__ float red1[8], red2[8];

    float s1 = 0.f, s2 = 0.f;
    #pragma unroll
    for (int q = 0; q < 3; q++) {
        const int d = tid + q * 256;
        const float x = __bfloat162float(hh[base + d]) + __bfloat162float(hl[base + d]);
        s1 += x * w1[d];
        s2 += x * w2[d];
    }
    #pragma unroll
    for (int o = 16; o; o >>= 1) {
        s1 += __shfl_xor_sync(0xFFFFFFFFu, s1, o);
        s2 += __shfl_xor_sync(0xFFFFFFFFu, s2, o);
    }
    if ((tid & 31) == 0) { red1[tid >> 5] = s1; red2[tid >> 5] = s2; }
    __syncthreads();
    if (tid == 0) {
        float t1 = 0.f, t2 = 0.f;
        #pragma unroll
        for (int w = 0; w < 8; w++) { t1 += red1[w]; t2 += red2[w]; }
        U[row] = t1 + cAll[l];
        W[row] = t2;
    }
}

// ===================== row softmax (+u,+w): fp32 in -> bf16 hi/lo out ================
__global__ __launch_bounds__(256)
void softmax_split(const float* __restrict__ P, const float* __restrict__ U,
                   const float* __restrict__ W,
                   __nv_bfloat16* __restrict__ Ph, __nv_bfloat16* __restrict__ Pl)
{
    const long row = blockIdx.x;
    const int tid = threadIdx.x;
    __shared__ float red[8];

    const float4 f = *(const float4*)(P + row * S_ + tid * 4);
    const long wbase = (row >> 10) << 10;              // b * S
    const float4 wv = *(const float4*)(W + wbase + tid * 4);
    const float uv = U[row];
    float v[4] = {f.x + uv + wv.x, f.y + uv + wv.y, f.z + uv + wv.z, f.w + uv + wv.w};

    float m = fmaxf(fmaxf(v[0], v[1]), fmaxf(v[2], v[3]));
    #pragma unroll
    for (int o = 16; o; o >>= 1) m = fmaxf(m, __shfl_xor_sync(0xFFFFFFFFu, m, o));
    if ((tid & 31) == 0) red[tid >> 5] = m;
    __syncthreads();
    if (tid < 8) {
        float t = red[tid];
        #pragma unroll
        for (int o = 4; o; o >>= 1) t = fmaxf(t, __shfl_xor_sync(0xFFu, t, o));
        if (tid == 0) red[0] = t;
    }
    __syncthreads();
    m = red[0];
    __syncthreads();

    float s = 0.f;
    #pragma unroll
    for (int k = 0; k < 4; k++) { v[k] = __expf(v[k] - m); s += v[k]; }
    #pragma unroll
    for (int o = 16; o; o >>= 1) s += __shfl_xor_sync(0xFFFFFFFFu, s, o);
    if ((tid & 31) == 0) red[tid >> 5] = s;
    __syncthreads();
    if (tid < 8) {
        float t = red[tid];
        #pragma unroll
        for (int o = 4; o; o >>= 1) t += __shfl_xor_sync(0xFFu, t, o);
        if (tid == 0) red[0] = t;
    }
    __syncthreads();
    const float inv = 1.f / red[0];

    __nv_bfloat16 h[4], l[4];
    #pragma unroll
    for (int k = 0; k < 4; k++) {
        const float p = v[k] * inv;
        h[k] = __float2bfloat16(p);
        l[k] = __float2bfloat16(p - __bfloat162float(h[k]));
    }
    *(uint2*)(Ph + row * S_ + tid * 4) = *(const uint2*)h;
    *(uint2*)(Pl + row * S_ + tid * 4) = *(const uint2*)l;
}

// ===================== fused last-layer pooled attention + head =====================
// Per batch b: G0 = h0 @ M; logit[j] = G0.h_j + u0 + W[j]; p = softmax; h0' = p @ V;
// out[b] = h0'.Whead + bhead.
__global__ __launch_bounds__(256)
void last_attn(const __nv_bfloat16* __restrict__ hh, const __nv_bfloat16* __restrict__ hl,
               const __nv_bfloat16* __restrict__ Mh, const __nv_bfloat16* __restrict__ Ml,
               const __nv_bfloat16* __restrict__ Vh, const __nv_bfloat16* __restrict__ Vl,
               const float* __restrict__ U, const float* __restrict__ W,
               const float* __restrict__ Whead, const float* __restrict__ bhead,
               float* __restrict__ out)
{
    __shared__ float h0[D_];
    __shared__ float G0[D_];
    __shared__ float lg[S_];
    __shared__ float h0n[D_];
    __shared__ float red[8];

    const int b = blockIdx.x;
    const int tid = threadIdx.x;
    const int lane = tid & 31, wid = tid >> 5;
    const long rowB = (long)b * S_;

    // h0 = pooled row (b, 0)
    for (int d = tid; d < D_; d += 256)
        h0[d] = __bfloat162float(hh[rowB * D_ + d]) + __bfloat162float(hl[rowB * D_ + d]);
    __syncthreads();

    // G0[c] = sum_d h0[d] * M[d, c]   (M row pitch NAUG)
    for (int c = tid; c < D_; c += 256) {
        float s = 0.f;
        for (int d = 0; d < D_; d++)
            s += h0[d] * (__bfloat162float(Mh[(long)d * NAUG + c]) +
                          __bfloat162float(Ml[(long)d * NAUG + c]));
        G0[c] = s;
    }
    __syncthreads();

    // logits: warp per j
    const float u0 = U[rowB];
    for (int j = wid; j < S_; j += 8) {
        const long hr = (rowB + j) * D_;
        float s = 0.f;
        for (int c = lane; c < D_; c += 32)
            s += (__bfloat162float(hh[hr + c]) + __bfloat162float(hl[hr + c])) * G0[c];
        #pragma unroll
        for (int o = 16; o; o >>= 1) s += __shfl_xor_sync(0xFFFFFFFFu, s, o);
        if (lane == 0) lg[j] = s + u0 + W[rowB + j];
    }
    __syncthreads();

    // softmax over lg[0..S_)
    float m = -1e30f;
    for (int j = tid; j < S_; j += 256) m = fmaxf(m, lg[j]);
    #pragma unroll
    for (int o = 16; o; o >>= 1) m = fmaxf(m, __shfl_xor_sync(0xFFFFFFFFu, m, o));
    if (lane == 0) red[wid] = m;
    __syncthreads();
    if (tid < 8) {
        float t = red[tid];
        #pragma unroll
        for (int o = 4; o; o >>= 1) t = fmaxf(t, __shfl_xor_sync(0xFFu, t, o));
        if (tid == 0) red[0] = t;
    }
    __syncthreads();
    m = red[0];
    __syncthreads();
    float sm = 0.f;
    for (int j = tid; j < S_; j += 256) {
        const float e = __expf(lg[j] - m);
        lg[j] = e;
        sm += e;
    }
    #pragma unroll
    for (int o = 16; o; o >>= 1) sm += __shfl_xor_sync(0xFFFFFFFFu, sm, o);
    if (lane == 0) red[wid] = sm;
    __syncthreads();
    if (tid < 8) {
        float t = red[tid];
        #pragma unroll
        for (int o = 4; o; o >>= 1) t += __shfl_xor_sync(0xFFu, t, o);
        if (tid == 0) red[0] = t;
    }
    __syncthreads();
    const float inv = 1.f / red[0];
    __syncthreads();

    // h0n[d] = sum_j p_j * V[j, d]  (V row pitch NAUG)
    for (int d = tid; d < D_; d += 256) {
        float s = 0.f;
        for (int j = 0; j < S_; j++)
            s += lg[j] * (__bfloat162float(Vh[(rowB + j) * NAUG + d]) +
                          __bfloat162float(Vl[(rowB + j) * NAUG + d]));
        h0n[d] = s * inv;
    }
    __syncthreads();

    // head
    float s = 0.f;
    for (int d = tid; d < D_; d += 256) s += h0n[d] * Whead[d];
    #pragma unroll
    for (int o = 16; o; o >>= 1) s += __shfl_xor_sync(0xFFFFFFFFu, s, o);
    if (lane == 0) red[wid] = s;
    __syncthreads();
    if (tid == 0) {
        float t = 0.f;
        #pragma unroll
        for (int w = 0; w < 8; w++) t += red[w];
        out[b] = t + bhead[0];
    }
}

// ===================== driver =====================
extern "C" void kernel_launch(void* const* d_in, const int* in_sizes, int n_in,
                              void* d_out, int out_size)
{
    const float* hs    = (const float*)d_in[0];
    const float* Wq    = (const float*)d_in[1];
    const float* bq    = (const float*)d_in[2];
    const float* Wk    = (const float*)d_in[3];
    const float* bk    = (const float*)d_in[4];
    const float* Wv    = (const float*)d_in[5];
    const float* bv    = (const float*)d_in[6];
    const float* lk    = (const float*)d_in[7];
    const float* lv    = (const float*)d_in[8];
    const float* Whead = (const float*)d_in[9];
    const float* bhead = (const float*)d_in[10];
    float* out = (float*)d_out;

    __nv_bfloat16 *hh, *hl, *GVh, *GVl, *Ph, *Pl, *Baugh, *Baugl;
    __nv_bfloat16 *Wqsh, *Wqsl, *Wksh, *Wksl;
    float *P, *biasVG, *cscVG, *w1, *w2, *U, *W, *cArr;
    cudaGetSymbolAddress((void**)&hh,   g_hh);    cudaGetSymbolAddress((void**)&hl,   g_hl);
    cudaGetSymbolAddress((void**)&GVh,  g_GVh);   cudaGetSymbolAddress((void**)&GVl,  g_GVl);
    cudaGetSymbolAddress((void**)&P,    g_P);
    cudaGetSymbolAddress((void**)&Ph,   g_Ph);    cudaGetSymbolAddress((void**)&Pl,   g_Pl);
    cudaGetSymbolAddress((void**)&Baugh, g_Baugh); cudaGetSymbolAddress((void**)&Baugl, g_Baugl);
    cudaGetSymbolAddress((void**)&Wqsh, g_Wqsh);  cudaGetSymbolAddress((void**)&Wqsl, g_Wqsl);
    cudaGetSymbolAddress((void**)&Wksh, g_Wksh);  cudaGetSymbolAddress((void**)&Wksl, g_Wksl);
    cudaGetSymbolAddress((void**)&biasVG, g_biasVG);
    cudaGetSymbolAddress((void**)&cscVG,  g_cscVG);
    cudaGetSymbolAddress((void**)&w1,   g_w1);    cudaGetSymbolAddress((void**)&w2,   g_w2);
    cudaGetSymbolAddress((void**)&U,    g_U);     cudaGetSymbolAddress((void**)&W,    g_W);
    cudaGetSymbolAddress((void**)&cArr, g_c);

    cudaFuncSetAttribute((const void*)gemm_mma<0,0>, cudaFuncAttributeMaxDynamicSharedMemorySize, GEMM_SMEM_NT);
    cudaFuncSetAttribute((const void*)gemm_mma<1,0>, cudaFuncAttributeMaxDynamicSharedMemorySize, GEMM_SMEM_NT);
    cudaFuncSetAttribute((const void*)gemm_mma<1,1>, cudaFuncAttributeMaxDynamicSharedMemorySize, GEMM_SMEM_NN);

    const float attn_alpha = 1.0f / sqrtf((float)D_);
    const long SD  = (long)S_ * D_;
    const long SS  = (long)S_ * S_;
    const long DD  = (long)D_ * D_;
    const long SGVl = (long)S_ * NAUG;

    const dim3 blk(256);

    // ================= one-time prep =================
    split_kernel<<<(MTOT * D_) / (256 * 4), blk>>>(hs, hh, hl);
    split_cs<<<dim3(DD / 1024, 1, L_), blk>>>(Wq, nullptr, Wqsh, Wqsl, D_, D_, 0, DD, 0, DD);
    split_cs<<<dim3(DD / 1024, 1, L_), blk>>>(Wk, lk,      Wksh, Wksl, D_, D_, 0, DD, (long)D_, DD);
    split_cs<<<dim3(DD / 1024, 1, L_), blk>>>(Wv, nullptr, Baugh, Baugl, D_, NAUG, VOFF, DD, 0, LB);
    gemm_mma<1,0><<<dim3(D_/BN, D_/BM, L_), blk, GEMM_SMEM_NT>>>(
        Wqsh, Wqsl, Wksh, Wksl, nullptr, Baugh, Baugl,
        nullptr, nullptr, attn_alpha, D_, D_, D_, NAUG, DD, DD, LB);
    wvec<<<dim3(3, 1, L_), blk>>>(Wq, Wk, bq, bk, lk, w1, w2, attn_alpha);
    c_kernel<<<L_, blk>>>(bq, bk, lk, cArr, attn_alpha);
    pack_vg<<<(L_ * NAUG) / 256, blk>>>(bv, lv, biasVG, cscVG);

    const dim3 grid_vg(NAUG / BN, MTOT / BM, 1);     // (12, 256, 1)
    const dim3 grid_qk(S_ / BN, S_ / BM, B_);        // (8, 8, 32)
    const dim3 grid_pv(D_ / BN, S_ / BM, B_);        // (6, 8, 32)

    for (int l = 0; l < L_ - 1; l++) {
        // GV = h @ [M | Wv]  (+biasVG)(*cscVG)  (NN)
        gemm_mma<1,1><<<grid_vg, blk, GEMM_SMEM_NN>>>(
            hh, hl, Baugh + (long)l * LB, Baugl + (long)l * LB, nullptr, GVh, GVl,
            biasVG + (long)l * NAUG, cscVG + (long)l * NAUG, 1.0f,
            D_, D_, NAUG, NAUG, 0, 0, 0);

        // u, w vectors from h (fp32 dots, off tensor pipe)
        uw_kernel<<<MTOT, blk>>>(hh, hl, w1 + (long)l * D_, w2 + (long)l * D_, cArr, l, U, W);

        // P = G @ h^T  (alpha already folded into M)  (NT, batched)
        gemm_mma<0,0><<<grid_qk, blk, GEMM_SMEM_NT>>>(
            GVh, GVl, hh, hl, P, nullptr, nullptr,
            nullptr, nullptr, 1.0f, D_, NAUG, D_, S_, SGVl, SD, SS);

        // softmax(P + u + w) -> split bf16
        softmax_split<<<B_ * S_, blk>>>(P, U, W, Ph, Pl);

        // h = P @ V  (V = GV cols 768.., NN trans-ldmatrix, batched)
        gemm_mma<1,1><<<grid_pv, blk, GEMM_SMEM_NN>>>(
            Ph, Pl, GVh + VOFF, GVl + VOFF, nullptr, hh, hl,
            nullptr, nullptr, 1.0f, S_, S_, NAUG, D_, SS, SGVl, SD);
    }

    // ===== last layer: only pooled row needed =====
    {
        const int l = L_ - 1;
        // V slab only: V = h @ Wv (+bv)(*lv)
        gemm_mma<1,1><<<dim3(D_ / BN, MTOT / BM, 1), blk, GEMM_SMEM_NN>>>(
            hh, hl, Baugh + (long)l * LB + VOFF, Baugl + (long)l * LB + VOFF,
            nullptr, GVh + VOFF, GVl + VOFF,
            biasVG + (long)l * NAUG + VOFF, cscVG + (long)l * NAUG + VOFF, 1.0f,
            D_, D_, NAUG, NAUG, 0, 0, 0);
        uw_kernel<<<MTOT, blk>>>(hh, hl, w1 + (long)l * D_, w2 + (long)l * D_, cArr, l, U, W);
        last_attn<<<B_, blk>>>(hh, hl, Baugh + (long)l * LB, Baugl + (long)l * LB,
                               GVh + VOFF, GVl + VOFF, U, W, Whead, bhead, out);
    }
}

// round 16
// speedup vs baseline: 1.0241x; 1.0241x over previous
#include <cuda_runtime.h>
#include <cuda_bf16.h>
#include <math.h>
#include <stdint.h>

#define B_ 32
#define S_ 1024
#define D_ 768
#define L_ 12
#define MTOT (B_*S_)
#define NAUG 1536                    // [M(768) | Wv(768)]
#define VOFF 768
#define LB ((long)D_*NAUG)           // per-layer Baug stride

// ===================== scratch (__device__ globals; no allocs) =====================
__device__ __align__(16) __nv_bfloat16 g_hh  [(size_t)MTOT*D_];
__device__ __align__(16) __nv_bfloat16 g_hl  [(size_t)MTOT*D_];
__device__ __align__(16) __nv_bfloat16 g_GVh [(size_t)MTOT*NAUG];   // [G | V]
__device__ __align__(16) __nv_bfloat16 g_GVl [(size_t)MTOT*NAUG];
__device__ __align__(16) float         g_P   [(size_t)B_*S_*S_];
__device__ __align__(16) __nv_bfloat16 g_Ph  [(size_t)B_*S_*S_];
__device__ __align__(16) __nv_bfloat16 g_Pl  [(size_t)B_*S_*S_];
__device__ __align__(16) __nv_bfloat16 g_Baugh[(size_t)L_*D_*NAUG];
__device__ __align__(16) __nv_bfloat16 g_Baugl[(size_t)L_*D_*NAUG];
__device__ __align__(16) __nv_bfloat16 g_Wqsh[(size_t)L_*D_*D_];    // Wq split (straight)
__device__ __align__(16) __nv_bfloat16 g_Wqsl[(size_t)L_*D_*D_];
__device__ __align__(16) __nv_bfloat16 g_Wksh[(size_t)L_*D_*D_];    // Wk*lk split
__device__ __align__(16) __nv_bfloat16 g_Wksl[(size_t)L_*D_*D_];
__device__ float g_biasVG[(size_t)L_*NAUG];
__device__ float g_cscVG [(size_t)L_*NAUG];
__device__ float g_w1[(size_t)L_*D_];    // alpha * Wq (lk .* bk)
__device__ float g_w2[(size_t)L_*D_];    // alpha * Wk (lk .* bq)
__device__ float g_U[MTOT];
__device__ float g_W[MTOT];
__device__ float g_c[L_];
__device__ float g_G0[B_*D_];
__device__ float g_Lg[MTOT];

// ===================== PTX helpers (generic sm_80+ features only) =====================
__device__ __forceinline__ uint32_t smem_u32(const void* p) {
    uint32_t a;
    asm("{ .reg .u64 t; cvta.to.shared.u64 t, %1; cvt.u32.u64 %0, t; }" : "=r"(a) : "l"(p));
    return a;
}
__device__ __forceinline__ void cpa16(uint32_t s, const void* g) {
    asm volatile("cp.async.cg.shared.global [%0], [%1], 16;" :: "r"(s), "l"(g));
}
#define CP_COMMIT() asm volatile("cp.async.commit_group;" ::: "memory")
#define CP_WAIT1()  asm volatile("cp.async.wait_group 1;" ::: "memory")

__device__ __forceinline__ void ldm_x4(uint32_t& r0, uint32_t& r1, uint32_t& r2, uint32_t& r3,
                                       uint32_t a) {
    asm volatile("ldmatrix.sync.aligned.m8n8.x4.shared.b16 {%0,%1,%2,%3}, [%4];"
                 : "=r"(r0), "=r"(r1), "=r"(r2), "=r"(r3) : "r"(a));
}
__device__ __forceinline__ void ldm_x4t(uint32_t& r0, uint32_t& r1, uint32_t& r2, uint32_t& r3,
                                        uint32_t a) {
    asm volatile("ldmatrix.sync.aligned.m8n8.x4.trans.shared.b16 {%0,%1,%2,%3}, [%4];"
                 : "=r"(r0), "=r"(r1), "=r"(r2), "=r"(r3) : "r"(a));
}
__device__ __forceinline__ void mma_bf16(float* c, const uint32_t* a, const uint32_t* b) {
    asm volatile("mma.sync.aligned.m16n8k16.row.col.f32.bf16.bf16.f32 "
                 "{%0,%1,%2,%3}, {%4,%5,%6,%7}, {%8,%9}, {%0,%1,%2,%3};"
                 : "+f"(c[0]), "+f"(c[1]), "+f"(c[2]), "+f"(c[3])
                 : "r"(a[0]), "r"(a[1]), "r"(a[2]), "r"(a[3]), "r"(b[0]), "r"(b[1]));
}

// ===================== GEMM ==============
#define BM 128
#define BN 128
#define BKE 32
#define ROWB 80
#define TILEB (128 * ROWB)            // 10240 B
#define BT_ROWB 272                   // 256B + 16B pad; 17 units mod 8 = 1
#define BT_TILE (32 * BT_ROWB)        // 8704 B

template<int OUT, int BTRANS>
__global__ __launch_bounds__(256, 2)
void gemm_mma(const __nv_bfloat16* __restrict__ Ah, const __nv_bfloat16* __restrict__ Al,
              const __nv_bfloat16* __restrict__ Bh, const __nv_bfloat16* __restrict__ Bl,
              float* __restrict__ Cf,
              __nv_bfloat16* __restrict__ Ch, __nv_bfloat16* __restrict__ Cl,
              const float* __restrict__ bias, const float* __restrict__ csc,
              float alpha, int K, int lda, int ldb, int ldc,
              long sA, long sB, long sC)
{
    constexpr int BTILEB = BTRANS ? BT_TILE : TILEB;
    constexpr int STAGEB = 2 * TILEB + 2 * BTILEB;

    extern __shared__ char smem[];
    const uint32_t sbase = smem_u32(smem);
    const int tid = threadIdx.x;
    const int lane = tid & 31, wid = tid >> 5;
    const int wm = wid & 3, wn = wid >> 2;
    const int z = blockIdx.z;
    Ah += z * sA;  Al += z * sA;
    Bh += z * sB;  Bl += z * sB;

    const long tileM = blockIdx.y * (long)BM;
    const long tileN = blockIdx.x * (long)BN;

    const __nv_bfloat16* gAh = Ah + tileM * lda;
    const __nv_bfloat16* gAl = Al + tileM * lda;
    const __nv_bfloat16* gBh = BTRANS ? Bh : (Bh + tileN * ldb);
    const __nv_bfloat16* gBl = BTRANS ? Bl : (Bl + tileN * ldb);

    const int r0q = tid >> 2, c0q = tid & 3;

    auto load_stage = [&](int stage, int k0) {
        const uint32_t sb = sbase + stage * STAGEB;
        #pragma unroll
        for (int it = 0; it < 2; it++) {
            const int r = r0q + it * 64;
            const long go = (long)r * lda + k0 + c0q * 8;
            const uint32_t so = r * ROWB + c0q * 16;
            cpa16(sb + 0 * TILEB + so, gAh + go);
            cpa16(sb + 1 * TILEB + so, gAl + go);
        }
        if (BTRANS) {
            #pragma unroll
            for (int it = 0; it < 2; it++) {
                const int idx = tid + it * 256;
                const int r = idx >> 4, c = idx & 15;
                const long go = (long)(k0 + r) * ldb + tileN + c * 8;
                const uint32_t so = r * BT_ROWB + c * 16;
                cpa16(sb + 2 * TILEB + so, gBh + go);
                cpa16(sb + 2 * TILEB + BTILEB + so, gBl + go);
            }
        } else {
            #pragma unroll
            for (int it = 0; it < 2; it++) {
                const int r = r0q + it * 64;
                const long gb = (long)r * ldb + k0 + c0q * 8;
                const uint32_t so = r * ROWB + c0q * 16;
                cpa16(sb + 2 * TILEB + so, gBh + gb);
                cpa16(sb + 2 * TILEB + BTILEB + so, gBl + gb);
            }
        }
        CP_COMMIT();
    };

    float acc[2][8][4];
    #pragma unroll
    for (int i = 0; i < 2; i++)
        #pragma unroll
        for (int j = 0; j < 8; j++)
            #pragma unroll
            for (int q = 0; q < 4; q++) acc[i][j][q] = 0.f;

    const int nk = K / BKE;
    load_stage(0, 0);
    load_stage(1, BKE);

    const int a_row  = wm * 32 + (lane & 15);
    const int b_row  = wn * 64 + (lane & 7) + ((lane >> 3) & 1) * 8;
    const int colb   = (lane >> 4) * 16;
    const int bt_k   = ((lane >> 4) & 1) * 8 + (lane & 7);
    const int bt_n   = wn * 64 + ((lane >> 3) & 1) * 8;

    for (int i = 0; i < nk; i++) {
        CP_WAIT1();
        __syncthreads();
        const uint32_t sb = sbase + (i & 1) * STAGEB;

        #pragma unroll
        for (int ks = 0; ks < 2; ks++) {
            uint32_t ah[2][4], al[2][4], bh[8][2], bl[8][2];
            #pragma unroll
            for (int ma = 0; ma < 2; ma++) {
                const uint32_t ad = sb + (a_row + ma * 16) * ROWB + ks * 32 + colb;
                ldm_x4(ah[ma][0], ah[ma][1], ah[ma][2], ah[ma][3], ad);
                ldm_x4(al[ma][0], al[ma][1], al[ma][2], al[ma][3], ad + TILEB);
            }
            #pragma unroll
            for (int nb = 0; nb < 4; nb++) {
                uint32_t t0, t1, t2, t3;
                if (BTRANS) {
                    const uint32_t bd = sb + 2 * TILEB
                                      + (ks * 16 + bt_k) * BT_ROWB
                                      + (bt_n + nb * 16) * 2;
                    ldm_x4t(t0, t1, t2, t3, bd);
                    bh[2*nb][0] = t0; bh[2*nb][1] = t2; bh[2*nb+1][0] = t1; bh[2*nb+1][1] = t3;
                    ldm_x4t(t0, t1, t2, t3, bd + BTILEB);
                    bl[2*nb][0] = t0; bl[2*nb][1] = t2; bl[2*nb+1][0] = t1; bl[2*nb+1][1] = t3;
                } else {
                    const uint32_t bd = sb + 2 * TILEB + (b_row + nb * 16) * ROWB + ks * 32 + colb;
                    ldm_x4(t0, t1, t2, t3, bd);
                    bh[2*nb][0] = t0; bh[2*nb][1] = t2; bh[2*nb+1][0] = t1; bh[2*nb+1][1] = t3;
                    ldm_x4(t0, t1, t2, t3, bd + BTILEB);
                    bl[2*nb][0] = t0; bl[2*nb][1] = t2; bl[2*nb+1][0] = t1; bl[2*nb+1][1] = t3;
                }
            }
            #pragma unroll
            for (int ma = 0; ma < 2; ma++)
                #pragma unroll
                for (int na = 0; na < 8; na++) mma_bf16(acc[ma][na], ah[ma], bh[na]);
            #pragma unroll
            for (int ma = 0; ma < 2; ma++)
                #pragma unroll
                for (int na = 0; na < 8; na++) mma_bf16(acc[ma][na], ah[ma], bl[na]);
            #pragma unroll
            for (int ma = 0; ma < 2; ma++)
                #pragma unroll
                for (int na = 0; na < 8; na++) mma_bf16(acc[ma][na], al[ma], bh[na]);
        }

        __syncthreads();
        if (i + 2 < nk) load_stage(i & 1, (i + 2) * BKE);
        else CP_COMMIT();
    }

    // ===================== epilogue =====================
    const int gq = lane >> 2, rq = lane & 3;
    #pragma unroll
    for (int ma = 0; ma < 2; ma++) {
        #pragma unroll
        for (int half = 0; half < 2; half++) {
            const long row = tileM + wm * 32 + ma * 16 + gq + half * 8;
            #pragma unroll
            for (int na = 0; na < 8; na++) {
                const long col = tileN + wn * 64 + na * 8 + rq * 2;
                float v0 = acc[ma][na][half * 2 + 0] * alpha;
                float v1 = acc[ma][na][half * 2 + 1] * alpha;
                if (bias) { v0 += bias[col]; v1 += bias[col + 1]; }
                if (csc)  { v0 *= csc[col];  v1 *= csc[col + 1]; }
                if (OUT == 0) {
                    float2 f2; f2.x = v0; f2.y = v1;
                    *(float2*)(Cf + z * sC + row * ldc + col) = f2;
                } else {
                    const __nv_bfloat16 h0 = __float2bfloat16(v0);
                    const __nv_bfloat16 h1 = __float2bfloat16(v1);
                    const __nv_bfloat16 l0 = __float2bfloat16(v0 - __bfloat162float(h0));
                    const __nv_bfloat16 l1 = __float2bfloat16(v1 - __bfloat162float(h1));
                    __nv_bfloat162 hp; hp.x = h0; hp.y = h1;
                    __nv_bfloat162 lp; lp.x = l0; lp.y = l1;
                    *(__nv_bfloat162*)(Ch + z * sC + row * ldc + col) = hp;
                    *(__nv_bfloat162*)(Cl + z * sC + row * ldc + col) = lp;
                }
            }
        }
    }
}

#define GEMM_SMEM_NT (2 * (2 * TILEB + 2 * TILEB))     // 81920
#define GEMM_SMEM_NN (2 * (2 * TILEB + 2 * BT_TILE))   // 75776

// ===================== elementwise fp32 -> bf16 hi/lo split (contiguous) ============
__global__ __launch_bounds__(256)
void split_kernel(const float* __restrict__ X, __nv_bfloat16* __restrict__ Xh,
                  __nv_bfloat16* __restrict__ Xl)
{
    const long i = ((long)blockIdx.x * 256 + threadIdx.x) * 4;
    const float4 f = *(const float4*)(X + i);
    float v[4] = {f.x, f.y, f.z, f.w};
    __nv_bfloat16 h[4], l[4];
    #pragma unroll
    for (int k = 0; k < 4; k++) {
        h[k] = __float2bfloat16(v[k]);
        l[k] = __float2bfloat16(v[k] - __bfloat162float(h[k]));
    }
    *(uint2*)(Xh + i) = *(const uint2*)h;
    *(uint2*)(Xl + i) = *(const uint2*)l;
}

// ===================== split with optional column scale, strided dst =================
__global__ __launch_bounds__(256)
void split_cs(const float* __restrict__ X, const float* __restrict__ sc,
              __nv_bfloat16* __restrict__ Dh, __nv_bfloat16* __restrict__ Dl,
              int C, int ldD, int off, long sX, long sSc, long sD)
{
    const int z = blockIdx.z;
    X += z * sX;
    if (sc) sc += z * sSc;
    Dh += z * sD;
    Dl += z * sD;
    const long idx = ((long)blockIdx.x * 256 + threadIdx.x) * 4;
    const int r = (int)(idx / C), c = (int)(idx % C);
    const float4 f = *(const float4*)(X + idx);
    float v[4] = {f.x, f.y, f.z, f.w};
    __nv_bfloat16 h[4], l[4];
    #pragma unroll
    for (int k = 0; k < 4; k++) {
        const float s = sc ? sc[c + k] : 1.0f;
        const float x = v[k] * s;
        h[k] = __float2bfloat16(x);
        l[k] = __float2bfloat16(x - __bfloat162float(h[k]));
    }
    const long o = (long)r * ldD + off + c;
    *(uint2*)(Dh + o) = *(const uint2*)h;
    *(uint2*)(Dl + o) = *(const uint2*)l;
}

// ===================== pack VG bias / csc =====================
__global__ __launch_bounds__(256)
void pack_vg(const float* __restrict__ bv, const float* __restrict__ lv,
             float* __restrict__ biasVG, float* __restrict__ cscVG)
{
    const int idx = blockIdx.x * 256 + threadIdx.x;    // over L_*NAUG = 18432 (exact)
    const int l = idx / NAUG, c = idx % NAUG;
    biasVG[idx] = (c >= VOFF) ? bv[l * D_ + (c - VOFF)] : 0.0f;
    cscVG[idx]  = (c >= VOFF) ? lv[l * D_ + (c - VOFF)] : 1.0f;
}

// ===================== bias-correction vectors (fp32) =====================
__global__ __launch_bounds__(256)
void wvec(const float* __restrict__ Wq, const float* __restrict__ Wk,
          const float* __restrict__ bq, const float* __restrict__ bk,
          const float* __restrict__ lk,
          float* __restrict__ w1, float* __restrict__ w2, float alpha)
{
    const int l = blockIdx.z;
    const int d = blockIdx.x * 256 + threadIdx.x;      // grid.x = 3
    const float* wq = Wq + (long)l * D_ * D_ + (long)d * D_;
    const float* wk = Wk + (long)l * D_ * D_ + (long)d * D_;
    const float* bqz = bq + (long)l * D_;
    const float* bkz = bk + (long)l * D_;
    const float* lkz = lk + (long)l * D_;
    float a1 = 0.f, a2 = 0.f;
    for (int e = 0; e < D_; e++) {
        const float le = lkz[e];
        a1 += wq[e] * le * bkz[e];
        a2 += wk[e] * le * bqz[e];
    }
    w1[(long)l * D_ + d] = alpha * a1;
    w2[(long)l * D_ + d] = alpha * a2;
}

// ===================== c constant per layer =====================
__global__ __launch_bounds__(256)
void c_kernel(const float* __restrict__ bq, const float* __restrict__ bk,
              const float* __restrict__ lk, float* __restrict__ cOut, float alpha)
{
    const int l = blockIdx.x;
    const int tid = threadIdx.x;
    __shared__ float red[8];
    float s = 0.f;
    for (int e = tid; e < D_; e += 256)
        s += bq[l * D_ + e] * lk[l * D_ + e] * bk[l * D_ + e];
    #pragma unroll
    for (int o = 16; o; o >>= 1) s += __shfl_xor_sync(0xFFFFFFFFu, s, o);
    if ((tid & 31) == 0) red[tid >> 5] = s;
    __syncthreads();
    if (tid == 0) {
        float t = 0.f;
        #pragma unroll
        for (int w = 0; w < 8; w++) t += red[w];
        cOut[l] = alpha * t;
    }
}

// ===================== u,w per row: dot(h, w1)+c, dot(h, w2) =====================
__global__ __launch_bounds__(256)
void uw_kernel(const __nv_bfloat16* __restrict__ hh, const __nv_bfloat16* __restrict__ hl,
               const float* __restrict__ w1, const float* __restrict__ w2,
               const float* __restrict__ cAll, int l,
               float* __restrict__ U, float* __restrict__ W)
{
    const long row = blockIdx.x;
    const long base = row * D_;
    const int tid = threadIdx.x;
    __shared__ float red1[8], red2[8];

    float s1 = 0.f, s2 = 0.f;
    #pragma unroll
    for (int q = 0; q < 3; q++) {
        const int d = tid + q * 256;
        const float x = __bfloat162float(hh[base + d]) + __bfloat162float(hl[base + d]);
        s1 += x * w1[d];
        s2 += x * w2[d];
    }
    #pragma unroll
    for (int o = 16; o; o >>= 1) {
        s1 += __shfl_xor_sync(0xFFFFFFFFu, s1, o);
        s2 += __shfl_xor_sync(0xFFFFFFFFu, s2, o);
    }
    if ((tid & 31) == 0) { red1[tid >> 5] = s1; red2[tid >> 5] = s2; }
    __syncthreads();
    if (tid == 0) {
        float t1 = 0.f, t2 = 0.f;
        #pragma unroll
        for (int w = 0; w < 8; w++) { t1 += red1[w]; t2 += red2[w]; }
        U[row] = t1 + cAll[l];
        W[row] = t2;
    }
}

// ===================== row softmax (+u,+w): fp32 in -> bf16 hi/lo out ================
__global__ __launch_bounds__(256)
void softmax_split(const float* __restrict__ P, const float* __restrict__ U,
                   const float* __restrict__ W,
                   __nv_bfloat16* __restrict__ Ph, __nv_bfloat16* __restrict__ Pl)
{
    const long row = blockIdx.x;
    const int tid = threadIdx.x;
    __shared__ float red[8];

    const float4 f = *(const float4*)(P + row * S_ + tid * 4);
    const long wbase = (row >> 10) << 10;              // b * S
    const float4 wv = *(const float4*)(W + wbase + tid * 4);
    const float uv = U[row];
    float v[4] = {f.x + uv + wv.x, f.y + uv + wv.y, f.z + uv + wv.z, f.w + uv + wv.w};

    float m = fmaxf(fmaxf(v[0], v[1]), fmaxf(v[2], v[3]));
    #pragma unroll
    for (int o = 16; o; o >>= 1) m = fmaxf(m, __shfl_xor_sync(0xFFFFFFFFu, m, o));
    if ((tid & 31) == 0) red[tid >> 5] = m;
    __syncthreads();
    if (tid < 8) {
        float t = red[tid];
        #pragma unroll
        for (int o = 4; o; o >>= 1) t = fmaxf(t, __shfl_xor_sync(0xFFu, t, o));
        if (tid == 0) red[0] = t;
    }
    __syncthreads();
    m = red[0];
    __syncthreads();

    float s = 0.f;
    #pragma unroll
    for (int k = 0; k < 4; k++) { v[k] = __expf(v[k] - m); s += v[k]; }
    #pragma unroll
    for (int o = 16; o; o >>= 1) s += __shfl_xor_sync(0xFFFFFFFFu, s, o);
    if ((tid & 31) == 0) red[tid >> 5] = s;
    __syncthreads();
    if (tid < 8) {
        float t = red[tid];
        #pragma unroll
        for (int o = 4; o; o >>= 1) t += __shfl_xor_sync(0xFFu, t, o);
        if (tid == 0) red[0] = t;
    }
    __syncthreads();
    const float inv = 1.f / red[0];

    __nv_bfloat16 h[4], l[4];
    #pragma unroll
    for (int k = 0; k < 4; k++) {
        const float p = v[k] * inv;
        h[k] = __float2bfloat16(p);
        l[k] = __float2bfloat16(p - __bfloat162float(h[k]));
    }
    *(uint2*)(Ph + row * S_ + tid * 4) = *(const uint2*)h;
    *(uint2*)(Pl + row * S_ + tid * 4) = *(const uint2*)l;
}

// ===================== pooled path: G0_b = h0_b @ M =====================
__global__ __launch_bounds__(256)
void g0_kernel(const __nv_bfloat16* __restrict__ hh, const __nv_bfloat16* __restrict__ hl,
               const __nv_bfloat16* __restrict__ Mh, const __nv_bfloat16* __restrict__ Ml,
               float* __restrict__ G0)
{
    __shared__ float h0[D_];
    const int b = blockIdx.x;
    const int tid = threadIdx.x;
    const long rowB = (long)b * S_;
    for (int d = tid; d < D_; d += 256)
        h0[d] = __bfloat162float(hh[rowB * D_ + d]) + __bfloat162float(hl[rowB * D_ + d]);
    __syncthreads();
    #pragma unroll
    for (int q = 0; q < 3; q++) {
        const int c = tid + q * 256;
        float s = 0.f;
        #pragma unroll 4
        for (int d = 0; d < D_; d++)
            s += h0[d] * (__bfloat162float(Mh[(long)d * NAUG + c]) +
                          __bfloat162float(Ml[(long)d * NAUG + c]));
        G0[b * D_ + c] = s;
    }
}

// ===================== pooled logits: lg[b,j] = G0_b . h_j + u0 + W[j] ==============
__global__ __launch_bounds__(256)
void logits_kernel(const __nv_bfloat16* __restrict__ hh, const __nv_bfloat16* __restrict__ hl,
                   const float* __restrict__ G0, const float* __restrict__ U,
                   const float* __restrict__ W, float* __restrict__ Lg)
{
    const long row = (long)blockIdx.x * 8 + (threadIdx.x >> 5);   // 4096 blocks x 8 warps
    const int lane = threadIdx.x & 31;
    const int b = (int)(row >> 10);
    const long hr = row * D_;
    const float* g0 = G0 + b * D_;
    float s = 0.f;
    #pragma unroll
    for (int q = 0; q < 24; q++) {
        const int c = lane + q * 32;
        s += (__bfloat162float(hh[hr + c]) + __bfloat162float(hl[hr + c])) * g0[c];
    }
    #pragma unroll
    for (int o = 16; o; o >>= 1) s += __shfl_xor_sync(0xFFFFFFFFu, s, o);
    if (lane == 0) Lg[row] = s + U[(long)b * S_] + W[row];
}

// ===================== pooled softmax: one row of S_ per block (in place) ===========
__global__ __launch_bounds__(256)
void softmax32(float* __restrict__ Lg)
{
    const int b = blockIdx.x;
    const int tid = threadIdx.x;
    float* p = Lg + (long)b * S_;
    __shared__ float red[8];

    float4 f = *(const float4*)(p + tid * 4);
    float v[4] = {f.x, f.y, f.z, f.w};
    float m = fmaxf(fmaxf(v[0], v[1]), fmaxf(v[2], v[3]));
    #pragma unroll
    for (int o = 16; o; o >>= 1) m = fmaxf(m, __shfl_xor_sync(0xFFFFFFFFu, m, o));
    if ((tid & 31) == 0) red[tid >> 5] = m;
    __syncthreads();
    if (tid < 8) {
        float t = red[tid];
        #pragma unroll
        for (int o = 4; o; o >>= 1) t = fmaxf(t, __shfl_xor_sync(0xFFu, t, o));
        if (tid == 0) red[0] = t;
    }
    __syncthreads();
    m = red[0];
    __syncthreads();
    float s = 0.f;
    #pragma unroll
    for (int k = 0; k < 4; k++) { v[k] = __expf(v[k] - m); s += v[k]; }
    #pragma unroll
    for (int o = 16; o; o >>= 1) s += __shfl_xor_sync(0xFFFFFFFFu, s, o);
    if ((tid & 31) == 0) red[tid >> 5] = s;
    __syncthreads();
    if (tid < 8) {
        float t = red[tid];
        #pragma unroll
        for (int o = 4; o; o >>= 1) t += __shfl_xor_sync(0xFFu, t, o);
        if (tid == 0) red[0] = t;
    }
    __syncthreads();
    const float inv = 1.f / red[0];
    f.x = v[0] * inv; f.y = v[1] * inv; f.z = v[2] * inv; f.w = v[3] * inv;
    *(float4*)(p + tid * 4) = f;
}

// ===================== pooled PV + head: out[b] = (p @ V) . Whead + bhead ===========
__global__ __launch_bounds__(256)
void pv_head(const float* __restrict__ Lg,
             const __nv_bfloat16* __restrict__ Vh, const __nv_bfloat16* __restrict__ Vl,
             const float* __restrict__ Whead, const float* __restrict__ bhead,
             float* __restrict__ out)
{
    __shared__ float pp[S_];
    __shared__ float red[8];
    const int b = blockIdx.x;
    const int tid = threadIdx.x;
    const long rowB = (long)b * S_;
    for (int j = tid; j < S_; j += 256) pp[j] = Lg[rowB + j];
    __syncthreads();

    float hs = 0.f;
    #pragma unroll
    for (int q = 0; q < 3; q++) {
        const int d = tid + q * 256;
        float s = 0.f;
        #pragma unroll 4
        for (int j = 0; j < S_; j++)
            s += pp[j] * (__bfloat162float(Vh[(rowB + j) * NAUG + d]) +
                          __bfloat162float(Vl[(rowB + j) * NAUG + d]));
        hs += s * Whead[d];
    }
    #pragma unroll
    for (int o = 16; o; o >>= 1) hs += __shfl_xor_sync(0xFFFFFFFFu, hs, o);
    if ((tid & 31) == 0) red[tid >> 5] = hs;
    __syncthreads();
    if (tid == 0) {
        float t = 0.f;
        #pragma unroll
        for (int w = 0; w < 8; w++) t += red[w];
        out[b] = t + bhead[0];
    }
}

// ===================== driver =====================
extern "C" void kernel_launch(void* const* d_in, const int* in_sizes, int n_in,
                              void* d_out, int out_size)
{
    const float* hs    = (const float*)d_in[0];
    const float* Wq    = (const float*)d_in[1];
    const float* bq    = (const float*)d_in[2];
    const float* Wk    = (const float*)d_in[3];
    const float* bk    = (const float*)d_in[4];
    const float* Wv    = (const float*)d_in[5];
    const float* bv    = (const float*)d_in[6];
    const float* lk    = (const float*)d_in[7];
    const float* lv    = (const float*)d_in[8];
    const float* Whead = (const float*)d_in[9];
    const float* bhead = (const float*)d_in[10];
    float* out = (float*)d_out;

    __nv_bfloat16 *hh, *hl, *GVh, *GVl, *Ph, *Pl, *Baugh, *Baugl;
    __nv_bfloat16 *Wqsh, *Wqsl, *Wksh, *Wksl;
    float *P, *biasVG, *cscVG, *w1, *w2, *U, *W, *cArr, *G0, *Lg;
    cudaGetSymbolAddress((void**)&hh,   g_hh);    cudaGetSymbolAddress((void**)&hl,   g_hl);
    cudaGetSymbolAddress((void**)&GVh,  g_GVh);   cudaGetSymbolAddress((void**)&GVl,  g_GVl);
    cudaGetSymbolAddress((void**)&P,    g_P);
    cudaGetSymbolAddress((void**)&Ph,   g_Ph);    cudaGetSymbolAddress((void**)&Pl,   g_Pl);
    cudaGetSymbolAddress((void**)&Baugh, g_Baugh); cudaGetSymbolAddress((void**)&Baugl, g_Baugl);
    cudaGetSymbolAddress((void**)&Wqsh, g_Wqsh);  cudaGetSymbolAddress((void**)&Wqsl, g_Wqsl);
    cudaGetSymbolAddress((void**)&Wksh, g_Wksh);  cudaGetSymbolAddress((void**)&Wksl, g_Wksl);
    cudaGetSymbolAddress((void**)&biasVG, g_biasVG);
    cudaGetSymbolAddress((void**)&cscVG,  g_cscVG);
    cudaGetSymbolAddress((void**)&w1,   g_w1);    cudaGetSymbolAddress((void**)&w2,   g_w2);
    cudaGetSymbolAddress((void**)&U,    g_U);     cudaGetSymbolAddress((void**)&W,    g_W);
    cudaGetSymbolAddress((void**)&cArr, g_c);
    cudaGetSymbolAddress((void**)&G0,   g_G0);    cudaGetSymbolAddress((void**)&Lg,   g_Lg);

    cudaFuncSetAttribute((const void*)gemm_mma<0,0>, cudaFuncAttributeMaxDynamicSharedMemorySize, GEMM_SMEM_NT);
    cudaFuncSetAttribute((const void*)gemm_mma<1,0>, cudaFuncAttributeMaxDynamicSharedMemorySize, GEMM_SMEM_NT);
    cudaFuncSetAttribute((const void*)gemm_mma<1,1>, cudaFuncAttributeMaxDynamicSharedMemorySize, GEMM_SMEM_NN);

    const float attn_alpha = 1.0f / sqrtf((float)D_);
    const long SD  = (long)S_ * D_;
    const long SS  = (long)S_ * S_;
    const long DD  = (long)D_ * D_;
    const long SGVl = (long)S_ * NAUG;

    const dim3 blk(256);

    // ================= one-time prep =================
    split_kernel<<<(MTOT * D_) / (256 * 4), blk>>>(hs, hh, hl);
    split_cs<<<dim3(DD / 1024, 1, L_), blk>>>(Wq, nullptr, Wqsh, Wqsl, D_, D_, 0, DD, 0, DD);
    split_cs<<<dim3(DD / 1024, 1, L_), blk>>>(Wk, lk,      Wksh, Wksl, D_, D_, 0, DD, (long)D_, DD);
    split_cs<<<dim3(DD / 1024, 1, L_), blk>>>(Wv, nullptr, Baugh, Baugl, D_, NAUG, VOFF, DD, 0, LB);
    gemm_mma<1,0><<<dim3(D_/BN, D_/BM, L_), blk, GEMM_SMEM_NT>>>(
        Wqsh, Wqsl, Wksh, Wksl, nullptr, Baugh, Baugl,
        nullptr, nullptr, attn_alpha, D_, D_, D_, NAUG, DD, DD, LB);
    wvec<<<dim3(3, 1, L_), blk>>>(Wq, Wk, bq, bk, lk, w1, w2, attn_alpha);
    c_kernel<<<L_, blk>>>(bq, bk, lk, cArr, attn_alpha);
    pack_vg<<<(L_ * NAUG) / 256, blk>>>(bv, lv, biasVG, cscVG);

    const dim3 grid_vg(NAUG / BN, MTOT / BM, 1);     // (12, 256, 1)
    const dim3 grid_qk(S_ / BN, S_ / BM, B_);        // (8, 8, 32)
    const dim3 grid_pv(D_ / BN, S_ / BM, B_);        // (6, 8, 32)

    for (int l = 0; l < L_ - 1; l++) {
        // GV = h @ [M | Wv]  (+biasVG)(*cscVG)  (NN)
        gemm_mma<1,1><<<grid_vg, blk, GEMM_SMEM_NN>>>(
            hh, hl, Baugh + (long)l * LB, Baugl + (long)l * LB, nullptr, GVh, GVl,
            biasVG + (long)l * NAUG, cscVG + (long)l * NAUG, 1.0f,
            D_, D_, NAUG, NAUG, 0, 0, 0);

        // u, w vectors from h (fp32 dots, off tensor pipe)
        uw_kernel<<<MTOT, blk>>>(hh, hl, w1 + (long)l * D_, w2 + (long)l * D_, cArr, l, U, W);

        // P = G @ h^T  (alpha already folded into M)  (NT, batched)
        gemm_mma<0,0><<<grid_qk, blk, GEMM_SMEM_NT>>>(
            GVh, GVl, hh, hl, P, nullptr, nullptr,
            nullptr, nullptr, 1.0f, D_, NAUG, D_, S_, SGVl, SD, SS);

        // softmax(P + u + w) -> split bf16
        softmax_split<<<B_ * S_, blk>>>(P, U, W, Ph, Pl);

        // h = P @ V  (V = GV cols 768.., NN trans-ldmatrix, batched)
        gemm_mma<1,1><<<grid_pv, blk, GEMM_SMEM_NN>>>(
            Ph, Pl, GVh + VOFF, GVl + VOFF, nullptr, hh, hl,
            nullptr, nullptr, 1.0f, S_, S_, NAUG, D_, SS, SGVl, SD);
    }

    // ===== last layer: only pooled row survives =====
    {
        const int l = L_ - 1;
        // V slab only: V = h @ Wv (+bv)(*lv)
        gemm_mma<1,1><<<dim3(D_ / BN, MTOT / BM, 1), blk, GEMM_SMEM_NN>>>(
            hh, hl, Baugh + (long)l * LB + VOFF, Baugl + (long)l * LB + VOFF,
            nullptr, GVh + VOFF, GVl + VOFF,
            biasVG + (long)l * NAUG + VOFF, cscVG + (long)l * NAUG + VOFF, 1.0f,
            D_, D_, NAUG, NAUG, 0, 0, 0);
        uw_kernel<<<MTOT, blk>>>(hh, hl, w1 + (long)l * D_, w2 + (long)l * D_, cArr, l, U, W);
        g0_kernel<<<B_, blk>>>(hh, hl, Baugh + (long)l * LB, Baugl + (long)l * LB, G0);
        logits_kernel<<<MTOT / 8, blk>>>(hh, hl, G0, U, W, Lg);
        softmax32<<<B_, blk>>>(Lg);
        pv_head<<<B_, blk>>>(Lg, GVh + VOFF, GVl + VOFF, Whead, bhead, out);
    }
}

// round 17
// speedup vs baseline: 1.0748x; 1.0494x over previous
#include <cuda_runtime.h>
#include <cuda_bf16.h>
#include <math.h>
#include <stdint.h>

#define B_ 32
#define S_ 1024
#define D_ 768
#define L_ 12
#define MTOT (B_*S_)
#define NAUG 1536                    // [M(768) | Wv(768)]
#define VOFF 768
#define LB ((long)D_*NAUG)           // per-layer Baug stride
#define NGRP 2
#define BG (B_/NGRP)                 // 16 batches per group
#define MG (BG*S_)                   // 16384 rows per group

// ===================== scratch (__device__ globals; no allocs) =====================
__device__ __align__(16) __nv_bfloat16 g_hh  [(size_t)MTOT*D_];
__device__ __align__(16) __nv_bfloat16 g_hl  [(size_t)MTOT*D_];
__device__ __align__(16) __nv_bfloat16 g_GVh [(size_t)MTOT*NAUG];   // [G | V]
__device__ __align__(16) __nv_bfloat16 g_GVl [(size_t)MTOT*NAUG];
__device__ __align__(16) float         g_P   [(size_t)B_*S_*S_];
__device__ __align__(16) __nv_bfloat16 g_Ph  [(size_t)B_*S_*S_];
__device__ __align__(16) __nv_bfloat16 g_Pl  [(size_t)B_*S_*S_];
__device__ __align__(16) __nv_bfloat16 g_Baugh[(size_t)L_*D_*NAUG];
__device__ __align__(16) __nv_bfloat16 g_Baugl[(size_t)L_*D_*NAUG];
__device__ __align__(16) __nv_bfloat16 g_Wqsh[(size_t)L_*D_*D_];    // Wq split (straight)
__device__ __align__(16) __nv_bfloat16 g_Wqsl[(size_t)L_*D_*D_];
__device__ __align__(16) __nv_bfloat16 g_Wksh[(size_t)L_*D_*D_];    // Wk*lk split
__device__ __align__(16) __nv_bfloat16 g_Wksl[(size_t)L_*D_*D_];
__device__ float g_biasVG[(size_t)L_*NAUG];
__device__ float g_cscVG [(size_t)L_*NAUG];
__device__ float g_w1[(size_t)L_*D_];    // alpha * Wq (lk .* bk)
__device__ float g_w2[(size_t)L_*D_];    // alpha * Wk (lk .* bq)
__device__ float g_U[MTOT];
__device__ float g_W[MTOT];
__device__ float g_c[L_];
__device__ float g_G0[B_*D_];
__device__ float g_Lg[MTOT];

// ===================== PTX helpers (generic sm_80+ features only) =====================
__device__ __forceinline__ uint32_t smem_u32(const void* p) {
    uint32_t a;
    asm("{ .reg .u64 t; cvta.to.shared.u64 t, %1; cvt.u32.u64 %0, t; }" : "=r"(a) : "l"(p));
    return a;
}
__device__ __forceinline__ void cpa16(uint32_t s, const void* g) {
    asm volatile("cp.async.cg.shared.global [%0], [%1], 16;" :: "r"(s), "l"(g));
}
#define CP_COMMIT() asm volatile("cp.async.commit_group;" ::: "memory")
#define CP_WAIT1()  asm volatile("cp.async.wait_group 1;" ::: "memory")

__device__ __forceinline__ void ldm_x4(uint32_t& r0, uint32_t& r1, uint32_t& r2, uint32_t& r3,
                                       uint32_t a) {
    asm volatile("ldmatrix.sync.aligned.m8n8.x4.shared.b16 {%0,%1,%2,%3}, [%4];"
                 : "=r"(r0), "=r"(r1), "=r"(r2), "=r"(r3) : "r"(a));
}
__device__ __forceinline__ void ldm_x4t(uint32_t& r0, uint32_t& r1, uint32_t& r2, uint32_t& r3,
                                        uint32_t a) {
    asm volatile("ldmatrix.sync.aligned.m8n8.x4.trans.shared.b16 {%0,%1,%2,%3}, [%4];"
                 : "=r"(r0), "=r"(r1), "=r"(r2), "=r"(r3) : "r"(a));
}
__device__ __forceinline__ void mma_bf16(float* c, const uint32_t* a, const uint32_t* b) {
    asm volatile("mma.sync.aligned.m16n8k16.row.col.f32.bf16.bf16.f32 "
                 "{%0,%1,%2,%3}, {%4,%5,%6,%7}, {%8,%9}, {%0,%1,%2,%3};"
                 : "+f"(c[0]), "+f"(c[1]), "+f"(c[2]), "+f"(c[3])
                 : "r"(a[0]), "r"(a[1]), "r"(a[2]), "r"(a[3]), "r"(b[0]), "r"(b[1]));
}

// ===================== GEMM ==============
#define BM 128
#define BN 128
#define BKE 32
#define ROWB 80
#define TILEB (128 * ROWB)            // 10240 B
#define BT_ROWB 272                   // 256B + 16B pad; 17 units mod 8 = 1
#define BT_TILE (32 * BT_ROWB)        // 8704 B

template<int OUT, int BTRANS>
__global__ __launch_bounds__(256, 2)
void gemm_mma(const __nv_bfloat16* __restrict__ Ah, const __nv_bfloat16* __restrict__ Al,
              const __nv_bfloat16* __restrict__ Bh, const __nv_bfloat16* __restrict__ Bl,
              float* __restrict__ Cf,
              __nv_bfloat16* __restrict__ Ch, __nv_bfloat16* __restrict__ Cl,
              const float* __restrict__ bias, const float* __restrict__ csc,
              float alpha, int K, int lda, int ldb, int ldc,
              long sA, long sB, long sC)
{
    constexpr int BTILEB = BTRANS ? BT_TILE : TILEB;
    constexpr int STAGEB = 2 * TILEB + 2 * BTILEB;

    extern __shared__ char smem[];
    const uint32_t sbase = smem_u32(smem);
    const int tid = threadIdx.x;
    const int lane = tid & 31, wid = tid >> 5;
    const int wm = wid & 3, wn = wid >> 2;
    const int z = blockIdx.z;
    Ah += z * sA;  Al += z * sA;
    Bh += z * sB;  Bl += z * sB;

    const long tileM = blockIdx.y * (long)BM;
    const long tileN = blockIdx.x * (long)BN;

    const __nv_bfloat16* gAh = Ah + tileM * lda;
    const __nv_bfloat16* gAl = Al + tileM * lda;
    const __nv_bfloat16* gBh = BTRANS ? Bh : (Bh + tileN * ldb);
    const __nv_bfloat16* gBl = BTRANS ? Bl : (Bl + tileN * ldb);

    const int r0q = tid >> 2, c0q = tid & 3;

    auto load_stage = [&](int stage, int k0) {
        const uint32_t sb = sbase + stage * STAGEB;
        #pragma unroll
        for (int it = 0; it < 2; it++) {
            const int r = r0q + it * 64;
            const long go = (long)r * lda + k0 + c0q * 8;
            const uint32_t so = r * ROWB + c0q * 16;
            cpa16(sb + 0 * TILEB + so, gAh + go);
            cpa16(sb + 1 * TILEB + so, gAl + go);
        }
        if (BTRANS) {
            #pragma unroll
            for (int it = 0; it < 2; it++) {
                const int idx = tid + it * 256;
                const int r = idx >> 4, c = idx & 15;
                const long go = (long)(k0 + r) * ldb + tileN + c * 8;
                const uint32_t so = r * BT_ROWB + c * 16;
                cpa16(sb + 2 * TILEB + so, gBh + go);
                cpa16(sb + 2 * TILEB + BTILEB + so, gBl + go);
            }
        } else {
            #pragma unroll
            for (int it = 0; it < 2; it++) {
                const int r = r0q + it * 64;
                const long gb = (long)r * ldb + k0 + c0q * 8;
                const uint32_t so = r * ROWB + c0q * 16;
                cpa16(sb + 2 * TILEB + so, gBh + gb);
                cpa16(sb + 2 * TILEB + BTILEB + so, gBl + gb);
            }
        }
        CP_COMMIT();
    };

    float acc[2][8][4];
    #pragma unroll
    for (int i = 0; i < 2; i++)
        #pragma unroll
        for (int j = 0; j < 8; j++)
            #pragma unroll
            for (int q = 0; q < 4; q++) acc[i][j][q] = 0.f;

    const int nk = K / BKE;
    load_stage(0, 0);
    load_stage(1, BKE);

    const int a_row  = wm * 32 + (lane & 15);
    const int b_row  = wn * 64 + (lane & 7) + ((lane >> 3) & 1) * 8;
    const int colb   = (lane >> 4) * 16;
    const int bt_k   = ((lane >> 4) & 1) * 8 + (lane & 7);
    const int bt_n   = wn * 64 + ((lane >> 3) & 1) * 8;

    for (int i = 0; i < nk; i++) {
        CP_WAIT1();
        __syncthreads();
        const uint32_t sb = sbase + (i & 1) * STAGEB;

        #pragma unroll
        for (int ks = 0; ks < 2; ks++) {
            uint32_t ah[2][4], al[2][4], bh[8][2], bl[8][2];
            #pragma unroll
            for (int ma = 0; ma < 2; ma++) {
                const uint32_t ad = sb + (a_row + ma * 16) * ROWB + ks * 32 + colb;
                ldm_x4(ah[ma][0], ah[ma][1], ah[ma][2], ah[ma][3], ad);
                ldm_x4(al[ma][0], al[ma][1], al[ma][2], al[ma][3], ad + TILEB);
            }
            #pragma unroll
            for (int nb = 0; nb < 4; nb++) {
                uint32_t t0, t1, t2, t3;
                if (BTRANS) {
                    const uint32_t bd = sb + 2 * TILEB
                                      + (ks * 16 + bt_k) * BT_ROWB
                                      + (bt_n + nb * 16) * 2;
                    ldm_x4t(t0, t1, t2, t3, bd);
                    bh[2*nb][0] = t0; bh[2*nb][1] = t2; bh[2*nb+1][0] = t1; bh[2*nb+1][1] = t3;
                    ldm_x4t(t0, t1, t2, t3, bd + BTILEB);
                    bl[2*nb][0] = t0; bl[2*nb][1] = t2; bl[2*nb+1][0] = t1; bl[2*nb+1][1] = t3;
                } else {
                    const uint32_t bd = sb + 2 * TILEB + (b_row + nb * 16) * ROWB + ks * 32 + colb;
                    ldm_x4(t0, t1, t2, t3, bd);
                    bh[2*nb][0] = t0; bh[2*nb][1] = t2; bh[2*nb+1][0] = t1; bh[2*nb+1][1] = t3;
                    ldm_x4(t0, t1, t2, t3, bd + BTILEB);
                    bl[2*nb][0] = t0; bl[2*nb][1] = t2; bl[2*nb+1][0] = t1; bl[2*nb+1][1] = t3;
                }
            }
            #pragma unroll
            for (int ma = 0; ma < 2; ma++)
                #pragma unroll
                for (int na = 0; na < 8; na++) mma_bf16(acc[ma][na], ah[ma], bh[na]);
            #pragma unroll
            for (int ma = 0; ma < 2; ma++)
                #pragma unroll
                for (int na = 0; na < 8; na++) mma_bf16(acc[ma][na], ah[ma], bl[na]);
            #pragma unroll
            for (int ma = 0; ma < 2; ma++)
                #pragma unroll
                for (int na = 0; na < 8; na++) mma_bf16(acc[ma][na], al[ma], bh[na]);
        }

        __syncthreads();
        if (i + 2 < nk) load_stage(i & 1, (i + 2) * BKE);
        else CP_COMMIT();
    }

    // ===================== epilogue =====================
    const int gq = lane >> 2, rq = lane & 3;
    #pragma unroll
    for (int ma = 0; ma < 2; ma++) {
        #pragma unroll
        for (int half = 0; half < 2; half++) {
            const long row = tileM + wm * 32 + ma * 16 + gq + half * 8;
            #pragma unroll
            for (int na = 0; na < 8; na++) {
                const long col = tileN + wn * 64 + na * 8 + rq * 2;
                float v0 = acc[ma][na][half * 2 + 0] * alpha;
                float v1 = acc[ma][na][half * 2 + 1] * alpha;
                if (bias) { v0 += bias[col]; v1 += bias[col + 1]; }
                if (csc)  { v0 *= csc[col];  v1 *= csc[col + 1]; }
                if (OUT == 0) {
                    float2 f2; f2.x = v0; f2.y = v1;
                    *(float2*)(Cf + z * sC + row * ldc + col) = f2;
                } else {
                    const __nv_bfloat16 h0 = __float2bfloat16(v0);
                    const __nv_bfloat16 h1 = __float2bfloat16(v1);
                    const __nv_bfloat16 l0 = __float2bfloat16(v0 - __bfloat162float(h0));
                    const __nv_bfloat16 l1 = __float2bfloat16(v1 - __bfloat162float(h1));
                    __nv_bfloat162 hp; hp.x = h0; hp.y = h1;
                    __nv_bfloat162 lp; lp.x = l0; lp.y = l1;
                    *(__nv_bfloat162*)(Ch + z * sC + row * ldc + col) = hp;
                    *(__nv_bfloat162*)(Cl + z * sC + row * ldc + col) = lp;
                }
            }
        }
    }
}

#define GEMM_SMEM_NT (2 * (2 * TILEB + 2 * TILEB))     // 81920
#define GEMM_SMEM_NN (2 * (2 * TILEB + 2 * BT_TILE))   // 75776

// ===================== elementwise fp32 -> bf16 hi/lo split (contiguous) ============
__global__ __launch_bounds__(256)
void split_kernel(const float* __restrict__ X, __nv_bfloat16* __restrict__ Xh,
                  __nv_bfloat16* __restrict__ Xl)
{
    const long i = ((long)blockIdx.x * 256 + threadIdx.x) * 4;
    const float4 f = *(const float4*)(X + i);
    float v[4] = {f.x, f.y, f.z, f.w};
    __nv_bfloat16 h[4], l[4];
    #pragma unroll
    for (int k = 0; k < 4; k++) {
        h[k] = __float2bfloat16(v[k]);
        l[k] = __float2bfloat16(v[k] - __bfloat162float(h[k]));
    }
    *(uint2*)(Xh + i) = *(const uint2*)h;
    *(uint2*)(Xl + i) = *(const uint2*)l;
}

// ===================== split with optional column scale, strided dst =================
__global__ __launch_bounds__(256)
void split_cs(const float* __restrict__ X, const float* __restrict__ sc,
              __nv_bfloat16* __restrict__ Dh, __nv_bfloat16* __restrict__ Dl,
              int C, int ldD, int off, long sX, long sSc, long sD)
{
    const int z = blockIdx.z;
    X += z * sX;
    if (sc) sc += z * sSc;
    Dh += z * sD;
    Dl += z * sD;
    const long idx = ((long)blockIdx.x * 256 + threadIdx.x) * 4;
    const int r = (int)(idx / C), c = (int)(idx % C);
    const float4 f = *(const float4*)(X + idx);
    float v[4] = {f.x, f.y, f.z, f.w};
    __nv_bfloat16 h[4], l[4];
    #pragma unroll
    for (int k = 0; k < 4; k++) {
        const float s = sc ? sc[c + k] : 1.0f;
        const float x = v[k] * s;
        h[k] = __float2bfloat16(x);
        l[k] = __float2bfloat16(x - __bfloat162float(h[k]));
    }
    const long o = (long)r * ldD + off + c;
    *(uint2*)(Dh + o) = *(const uint2*)h;
    *(uint2*)(Dl + o) = *(const uint2*)l;
}

// ===================== pack VG bias / csc =====================
__global__ __launch_bounds__(256)
void pack_vg(const float* __restrict__ bv, const float* __restrict__ lv,
             float* __restrict__ biasVG, float* __restrict__ cscVG)
{
    const int idx = blockIdx.x * 256 + threadIdx.x;    // over L_*NAUG = 18432 (exact)
    const int l = idx / NAUG, c = idx % NAUG;
    biasVG[idx] = (c >= VOFF) ? bv[l * D_ + (c - VOFF)] : 0.0f;
    cscVG[idx]  = (c >= VOFF) ? lv[l * D_ + (c - VOFF)] : 1.0f;
}

// ===================== bias-correction vectors (fp32) =====================
__global__ __launch_bounds__(256)
void wvec(const float* __restrict__ Wq, const float* __restrict__ Wk,
          const float* __restrict__ bq, const float* __restrict__ bk,
          const float* __restrict__ lk,
          float* __restrict__ w1, float* __restrict__ w2, float alpha)
{
    const int l = blockIdx.z;
    const int d = blockIdx.x * 256 + threadIdx.x;      // grid.x = 3
    const float* wq = Wq + (long)l * D_ * D_ + (long)d * D_;
    const float* wk = Wk + (long)l * D_ * D_ + (long)d * D_;
    const float* bqz = bq + (long)l * D_;
    const float* bkz = bk + (long)l * D_;
    const float* lkz = lk + (long)l * D_;
    float a1 = 0.f, a2 = 0.f;
    for (int e = 0; e < D_; e++) {
        const float le = lkz[e];
        a1 += wq[e] * le * bkz[e];
        a2 += wk[e] * le * bqz[e];
    }
    w1[(long)l * D_ + d] = alpha * a1;
    w2[(long)l * D_ + d] = alpha * a2;
}

// ===================== c constant per layer =====================
__global__ __launch_bounds__(256)
void c_kernel(const float* __restrict__ bq, const float* __restrict__ bk,
              const float* __restrict__ lk, float* __restrict__ cOut, float alpha)
{
    const int l = blockIdx.x;
    const int tid = threadIdx.x;
    __shared__ float red[8];
    float s = 0.f;
    for (int e = tid; e < D_; e += 256)
        s += bq[l * D_ + e] * lk[l * D_ + e] * bk[l * D_ + e];
    #pragma unroll
    for (int o = 16; o; o >>= 1) s += __shfl_xor_sync(0xFFFFFFFFu, s, o);
    if ((tid & 31) == 0) red[tid >> 5] = s;
    __syncthreads();
    if (tid == 0) {
        float t = 0.f;
        #pragma unroll
        for (int w = 0; w < 8; w++) t += red[w];
        cOut[l] = alpha * t;
    }
}

// ===================== u,w per row: dot(h, w1)+c, dot(h, w2) =====================
__global__ __launch_bounds__(256)
void uw_kernel(const __nv_bfloat16* __restrict__ hh, const __nv_bfloat16* __restrict__ hl,
               const float* __restrict__ w1, const float* __restrict__ w2,
               const float* __restrict__ cAll, int l,
               float* __restrict__ U, float* __restrict__ W)
{
    const long row = blockIdx.x;
    const long base = row * D_;
    const int tid = threadIdx.x;
    __shared__ float red1[8], red2[8];

    float s1 = 0.f, s2 = 0.f;
    #pragma unroll
    for (int q = 0; q < 3; q++) {
        const int d = tid + q * 256;
        const float x = __bfloat162float(hh[base + d]) + __bfloat162float(hl[base + d]);
        s1 += x * w1[d];
        s2 += x * w2[d];
    }
    #pragma unroll
    for (int o = 16; o; o >>= 1) {
        s1 += __shfl_xor_sync(0xFFFFFFFFu, s1, o);
        s2 += __shfl_xor_sync(0xFFFFFFFFu, s2, o);
    }
    if ((tid & 31) == 0) { red1[tid >> 5] = s1; red2[tid >> 5] = s2; }
    __syncthreads();
    if (tid == 0) {
        float t1 = 0.f, t2 = 0.f;
        #pragma unroll
        for (int w = 0; w < 8; w++) { t1 += red1[w]; t2 += red2[w]; }
        U[row] = t1 + cAll[l];
        W[row] = t2;
    }
}

// ===================== row softmax (+u,+w): fp32 in -> bf16 hi/lo out ================
__global__ __launch_bounds__(256)
void softmax_split(const float* __restrict__ P, const float* __restrict__ U,
                   const float* __restrict__ W,
                   __nv_bfloat16* __restrict__ Ph, __nv_bfloat16* __restrict__ Pl)
{
    const long row = blockIdx.x;
    const int tid = threadIdx.x;
    __shared__ float red[8];

    const float4 f = *(const float4*)(P + row * S_ + tid * 4);
    const long wbase = (row >> 10) << 10;              // b * S (group-local)
    const float4 wv = *(const float4*)(W + wbase + tid * 4);
    const float uv = U[row];
    float v[4] = {f.x + uv + wv.x, f.y + uv + wv.y, f.z + uv + wv.z, f.w + uv + wv.w};

    float m = fmaxf(fmaxf(v[0], v[1]), fmaxf(v[2], v[3]));
    #pragma unroll
    for (int o = 16; o; o >>= 1) m = fmaxf(m, __shfl_xor_sync(0xFFFFFFFFu, m, o));
    if ((tid & 31) == 0) red[tid >> 5] = m;
    __syncthreads();
    if (tid < 8) {
        float t = red[tid];
        #pragma unroll
        for (int o = 4; o; o >>= 1) t = fmaxf(t, __shfl_xor_sync(0xFFu, t, o));
        if (tid == 0) red[0] = t;
    }
    __syncthreads();
    m = red[0];
    __syncthreads();

    float s = 0.f;
    #pragma unroll
    for (int k = 0; k < 4; k++) { v[k] = __expf(v[k] - m); s += v[k]; }
    #pragma unroll
    for (int o = 16; o; o >>= 1) s += __shfl_xor_sync(0xFFFFFFFFu, s, o);
    if ((tid & 31) == 0) red[tid >> 5] = s;
    __syncthreads();
    if (tid < 8) {
        float t = red[tid];
        #pragma unroll
        for (int o = 4; o; o >>= 1) t += __shfl_xor_sync(0xFFu, t, o);
        if (tid == 0) red[0] = t;
    }
    __syncthreads();
    const float inv = 1.f / red[0];

    __nv_bfloat16 h[4], l[4];
    #pragma unroll
    for (int k = 0; k < 4; k++) {
        const float p = v[k] * inv;
        h[k] = __float2bfloat16(p);
        l[k] = __float2bfloat16(p - __bfloat162float(h[k]));
    }
    *(uint2*)(Ph + row * S_ + tid * 4) = *(const uint2*)h;
    *(uint2*)(Pl + row * S_ + tid * 4) = *(const uint2*)l;
}

// ===================== pooled path: G0_b = h0_b @ M =====================
__global__ __launch_bounds__(256)
void g0_kernel(const __nv_bfloat16* __restrict__ hh, const __nv_bfloat16* __restrict__ hl,
               const __nv_bfloat16* __restrict__ Mh, const __nv_bfloat16* __restrict__ Ml,
               float* __restrict__ G0)
{
    __shared__ float h0[D_];
    const int b = blockIdx.x;
    const int tid = threadIdx.x;
    const long rowB = (long)b * S_;
    for (int d = tid; d < D_; d += 256)
        h0[d] = __bfloat162float(hh[rowB * D_ + d]) + __bfloat162float(hl[rowB * D_ + d]);
    __syncthreads();
    #pragma unroll
    for (int q = 0; q < 3; q++) {
        const int c = tid + q * 256;
        float s = 0.f;
        #pragma unroll 4
        for (int d = 0; d < D_; d++)
            s += h0[d] * (__bfloat162float(Mh[(long)d * NAUG + c]) +
                          __bfloat162float(Ml[(long)d * NAUG + c]));
        G0[b * D_ + c] = s;
    }
}

// ===================== pooled logits: lg[b,j] = G0_b . h_j + u0 + W[j] ==============
__global__ __launch_bounds__(256)
void logits_kernel(const __nv_bfloat16* __restrict__ hh, const __nv_bfloat16* __restrict__ hl,
                   const float* __restrict__ G0, const float* __restrict__ U,
                   const float* __restrict__ W, float* __restrict__ Lg)
{
    const long row = (long)blockIdx.x * 8 + (threadIdx.x >> 5);
    const int lane = threadIdx.x & 31;
    const int b = (int)(row >> 10);
    const long hr = row * D_;
    const float* g0 = G0 + b * D_;
    float s = 0.f;
    #pragma unroll
    for (int q = 0; q < 24; q++) {
        const int c = lane + q * 32;
        s += (__bfloat162float(hh[hr + c]) + __bfloat162float(hl[hr + c])) * g0[c];
    }
    #pragma unroll
    for (int o = 16; o; o >>= 1) s += __shfl_xor_sync(0xFFFFFFFFu, s, o);
    if (lane == 0) Lg[row] = s + U[(long)b * S_] + W[row];
}

// ===================== pooled softmax: one row of S_ per block (in place) ===========
__global__ __launch_bounds__(256)
void softmax32(float* __restrict__ Lg)
{
    const int b = blockIdx.x;
    const int tid = threadIdx.x;
    float* p = Lg + (long)b * S_;
    __shared__ float red[8];

    float4 f = *(const float4*)(p + tid * 4);
    float v[4] = {f.x, f.y, f.z, f.w};
    float m = fmaxf(fmaxf(v[0], v[1]), fmaxf(v[2], v[3]));
    #pragma unroll
    for (int o = 16; o; o >>= 1) m = fmaxf(m, __shfl_xor_sync(0xFFFFFFFFu, m, o));
    if ((tid & 31) == 0) red[tid >> 5] = m;
    __syncthreads();
    if (tid < 8) {
        float t = red[tid];
        #pragma unroll
        for (int o = 4; o; o >>= 1) t = fmaxf(t, __shfl_xor_sync(0xFFu, t, o));
        if (tid == 0) red[0] = t;
    }
    __syncthreads();
    m = red[0];
    __syncthreads();
    float s = 0.f;
    #pragma unroll
    for (int k = 0; k < 4; k++) { v[k] = __expf(v[k] - m); s += v[k]; }
    #pragma unroll
    for (int o = 16; o; o >>= 1) s += __shfl_xor_sync(0xFFFFFFFFu, s, o);
    if ((tid & 31) == 0) red[tid >> 5] = s;
    __syncthreads();
    if (tid < 8) {
        float t = red[tid];
        #pragma unroll
        for (int o = 4; o; o >>= 1) t += __shfl_xor_sync(0xFFu, t, o);
        if (tid == 0) red[0] = t;
    }
    __syncthreads();
    const float inv = 1.f / red[0];
    f.x = v[0] * inv; f.y = v[1] * inv; f.z = v[2] * inv; f.w = v[3] * inv;
    *(float4*)(p + tid * 4) = f;
}

// ===================== pooled PV + head: out[b] = (p @ V) . Whead + bhead ===========
__global__ __launch_bounds__(256)
void pv_head(const float* __restrict__ Lg,
             const __nv_bfloat16* __restrict__ Vh, const __nv_bfloat16* __restrict__ Vl,
             const float* __restrict__ Whead, const float* __restrict__ bhead,
             float* __restrict__ out)
{
    __shared__ float pp[S_];
    __shared__ float red[8];
    const int b = blockIdx.x;
    const int tid = threadIdx.x;
    const long rowB = (long)b * S_;
    for (int j = tid; j < S_; j += 256) pp[j] = Lg[rowB + j];
    __syncthreads();

    float hs = 0.f;
    #pragma unroll
    for (int q = 0; q < 3; q++) {
        const int d = tid + q * 256;
        float s = 0.f;
        #pragma unroll 4
        for (int j = 0; j < S_; j++)
            s += pp[j] * (__bfloat162float(Vh[(rowB + j) * NAUG + d]) +
                          __bfloat162float(Vl[(rowB + j) * NAUG + d]));
        hs += s * Whead[d];
    }
    #pragma unroll
    for (int o = 16; o; o >>= 1) hs += __shfl_xor_sync(0xFFFFFFFFu, hs, o);
    if ((tid & 31) == 0) red[tid >> 5] = hs;
    __syncthreads();
    if (tid == 0) {
        float t = 0.f;
        #pragma unroll
        for (int w = 0; w < 8; w++) t += red[w];
        out[b] = t + bhead[0];
    }
}

// ===================== driver =====================
extern "C" void kernel_launch(void* const* d_in, const int* in_sizes, int n_in,
                              void* d_out, int out_size)
{
    const float* hs    = (const float*)d_in[0];
    const float* Wq    = (const float*)d_in[1];
    const float* bq    = (const float*)d_in[2];
    const float* Wk    = (const float*)d_in[3];
    const float* bk    = (const float*)d_in[4];
    const float* Wv    = (const float*)d_in[5];
    const float* bv    = (const float*)d_in[6];
    const float* lk    = (const float*)d_in[7];
    const float* lv    = (const float*)d_in[8];
    const float* Whead = (const float*)d_in[9];
    const float* bhead = (const float*)d_in[10];
    float* out = (float*)d_out;

    __nv_bfloat16 *hh, *hl, *GVh, *GVl, *Ph, *Pl, *Baugh, *Baugl;
    __nv_bfloat16 *Wqsh, *Wqsl, *Wksh, *Wksl;
    float *P, *biasVG, *cscVG, *w1, *w2, *U, *W, *cArr, *G0, *Lg;
    cudaGetSymbolAddress((void**)&hh,   g_hh);    cudaGetSymbolAddress((void**)&hl,   g_hl);
    cudaGetSymbolAddress((void**)&GVh,  g_GVh);   cudaGetSymbolAddress((void**)&GVl,  g_GVl);
    cudaGetSymbolAddress((void**)&P,    g_P);
    cudaGetSymbolAddress((void**)&Ph,   g_Ph);    cudaGetSymbolAddress((void**)&Pl,   g_Pl);
    cudaGetSymbolAddress((void**)&Baugh, g_Baugh); cudaGetSymbolAddress((void**)&Baugl, g_Baugl);
    cudaGetSymbolAddress((void**)&Wqsh, g_Wqsh);  cudaGetSymbolAddress((void**)&Wqsl, g_Wqsl);
    cudaGetSymbolAddress((void**)&Wksh, g_Wksh);  cudaGetSymbolAddress((void**)&Wksl, g_Wksl);
    cudaGetSymbolAddress((void**)&biasVG, g_biasVG);
    cudaGetSymbolAddress((void**)&cscVG,  g_cscVG);
    cudaGetSymbolAddress((void**)&w1,   g_w1);    cudaGetSymbolAddress((void**)&w2,   g_w2);
    cudaGetSymbolAddress((void**)&U,    g_U);     cudaGetSymbolAddress((void**)&W,    g_W);
    cudaGetSymbolAddress((void**)&cArr, g_c);
    cudaGetSymbolAddress((void**)&G0,   g_G0);    cudaGetSymbolAddress((void**)&Lg,   g_Lg);

    cudaFuncSetAttribute((const void*)gemm_mma<0,0>, cudaFuncAttributeMaxDynamicSharedMemorySize, GEMM_SMEM_NT);
    cudaFuncSetAttribute((const void*)gemm_mma<1,0>, cudaFuncAttributeMaxDynamicSharedMemorySize, GEMM_SMEM_NT);
    cudaFuncSetAttribute((const void*)gemm_mma<1,1>, cudaFuncAttributeMaxDynamicSharedMemorySize, GEMM_SMEM_NN);

    const float attn_alpha = 1.0f / sqrtf((float)D_);
    const long SD  = (long)S_ * D_;
    const long SS  = (long)S_ * S_;
    const long DD  = (long)D_ * D_;
    const long SGVl = (long)S_ * NAUG;

    const dim3 blk(256);

    // streams + events for capture-safe fork/join
    cudaStream_t s2;
    cudaStreamCreateWithFlags(&s2, cudaStreamNonBlocking);
    cudaEvent_t evPrep, evJoin;
    cudaEventCreateWithFlags(&evPrep, cudaEventDisableTiming);
    cudaEventCreateWithFlags(&evJoin, cudaEventDisableTiming);

    // ================= one-time prep (stream 0) =================
    split_kernel<<<(MTOT * D_) / (256 * 4), blk>>>(hs, hh, hl);
    split_cs<<<dim3(DD / 1024, 1, L_), blk>>>(Wq, nullptr, Wqsh, Wqsl, D_, D_, 0, DD, 0, DD);
    split_cs<<<dim3(DD / 1024, 1, L_), blk>>>(Wk, lk,      Wksh, Wksl, D_, D_, 0, DD, (long)D_, DD);
    split_cs<<<dim3(DD / 1024, 1, L_), blk>>>(Wv, nullptr, Baugh, Baugl, D_, NAUG, VOFF, DD, 0, LB);
    gemm_mma<1,0><<<dim3(D_/BN, D_/BM, L_), blk, GEMM_SMEM_NT>>>(
        Wqsh, Wqsl, Wksh, Wksl, nullptr, Baugh, Baugl,
        nullptr, nullptr, attn_alpha, D_, D_, D_, NAUG, DD, DD, LB);
    wvec<<<dim3(3, 1, L_), blk>>>(Wq, Wk, bq, bk, lk, w1, w2, attn_alpha);
    c_kernel<<<L_, blk>>>(bq, bk, lk, cArr, attn_alpha);
    pack_vg<<<(L_ * NAUG) / 256, blk>>>(bv, lv, biasVG, cscVG);

    // fork: s2 waits for prep
    cudaEventRecord(evPrep, 0);
    cudaStreamWaitEvent(s2, evPrep, 0);

    const dim3 grid_vg(NAUG / BN, MG / BM, 1);      // (12, 128)
    const dim3 grid_qk(S_ / BN, S_ / BM, BG);       // (8, 8, 16)
    const dim3 grid_pv(D_ / BN, S_ / BM, BG);       // (6, 8, 16)

    // per-group chain
    auto run_group = [&](int g, cudaStream_t st) {
        __nv_bfloat16* ghh = hh + (size_t)g * MG * D_;
        __nv_bfloat16* ghl = hl + (size_t)g * MG * D_;
        __nv_bfloat16* gGVh = GVh + (size_t)g * MG * NAUG;
        __nv_bfloat16* gGVl = GVl + (size_t)g * MG * NAUG;
        float* gP  = P  + (size_t)g * MG * S_;
        __nv_bfloat16* gPh = Ph + (size_t)g * MG * S_;
        __nv_bfloat16* gPl = Pl + (size_t)g * MG * S_;
        float* gU = U + (size_t)g * MG;
        float* gW = W + (size_t)g * MG;
        float* gG0 = G0 + (size_t)g * BG * D_;
        float* gLg = Lg + (size_t)g * MG;

        for (int l = 0; l < L_ - 1; l++) {
            gemm_mma<1,1><<<grid_vg, blk, GEMM_SMEM_NN, st>>>(
                ghh, ghl, Baugh + (long)l * LB, Baugl + (long)l * LB, nullptr, gGVh, gGVl,
                biasVG + (long)l * NAUG, cscVG + (long)l * NAUG, 1.0f,
                D_, D_, NAUG, NAUG, 0, 0, 0);
            uw_kernel<<<MG, blk, 0, st>>>(ghh, ghl, w1 + (long)l * D_, w2 + (long)l * D_,
                                          cArr, l, gU, gW);
            gemm_mma<0,0><<<grid_qk, blk, GEMM_SMEM_NT, st>>>(
                gGVh, gGVl, ghh, ghl, gP, nullptr, nullptr,
                nullptr, nullptr, 1.0f, D_, NAUG, D_, S_, SGVl, SD, SS);
            softmax_split<<<MG, blk, 0, st>>>(gP, gU, gW, gPh, gPl);
            gemm_mma<1,1><<<grid_pv, blk, GEMM_SMEM_NN, st>>>(
                gPh, gPl, gGVh + VOFF, gGVl + VOFF, nullptr, ghh, ghl,
                nullptr, nullptr, 1.0f, S_, S_, NAUG, D_, SS, SGVl, SD);
        }

        // last layer: only pooled row survives
        {
            const int l = L_ - 1;
            gemm_mma<1,1><<<dim3(D_ / BN, MG / BM, 1), blk, GEMM_SMEM_NN, st>>>(
                ghh, ghl, Baugh + (long)l * LB + VOFF, Baugl + (long)l * LB + VOFF,
                nullptr, gGVh + VOFF, gGVl + VOFF,
                biasVG + (long)l * NAUG + VOFF, cscVG + (long)l * NAUG + VOFF, 1.0f,
                D_, D_, NAUG, NAUG, 0, 0, 0);
            uw_kernel<<<MG, blk, 0, st>>>(ghh, ghl, w1 + (long)l * D_, w2 + (long)l * D_,
                                          cArr, l, gU, gW);
            g0_kernel<<<BG, blk, 0, st>>>(ghh, ghl, Baugh + (long)l * LB, Baugl + (long)l * LB, gG0);
            logits_kernel<<<MG / 8, blk, 0, st>>>(ghh, ghl, gG0, gU, gW, gLg);
            softmax32<<<BG, blk, 0, st>>>(gLg);
            pv_head<<<BG, blk, 0, st>>>(gLg, gGVh + VOFF, gGVl + VOFF, Whead, bhead,
                                        out + g * BG);
        }
    };

    run_group(0, 0);
    run_group(1, s2);

    // join s2 back to origin stream (required for capture)
    cudaEventRecord(evJoin, s2);
    cudaStreamWaitEvent(0, evJoin, 0);
}